// round 2
// baseline (speedup 1.0000x reference)
#include <cuda_runtime.h>
#include <cuda_bf16.h>
#include <math.h>

// Problem constants (fixed shapes for GraphAttentionLayer_18021682774974)
#define Bb     32
#define Nn     1024
#define Cc     1024
#define Hh     8
#define Dd     128
#define BHn    (Bb * Hh)            // 256
#define MROWS  (Bb * Nn)            // 32768
#define XSZ    (Bb * Hh * Nn * Dd)  // 33554432

// Scratch (device-global; no cudaMalloc allowed)
__device__ float g_X [XSZ];   // x  in [b, h, n, d] layout, i.e. [bh][n][d]
__device__ float g_XM[XSZ];   // x@M in [bh][n][d]
__device__ float g_O [XSZ];   // attention out in [bh][n][d]

// ---------------------------------------------------------------------------
// Kernel 1: X = h @ W^T + bias, scattered into [bh][n][d] layout.
// A = h [32768 x 1024] (K contiguous), B = W [1024 x 1024] rows=out col (K contiguous).
// 128x128 block tile, BK=16, 256 threads, 8x8 per thread (split 4+4 rows/cols).
// ---------------------------------------------------------------------------
__global__ void __launch_bounds__(256) k_gemm_xw(const float* __restrict__ A,
                                                 const float* __restrict__ Wm,
                                                 const float* __restrict__ bias)
{
    __shared__ float As[16][128];   // transposed: As[k][m]
    __shared__ float Bs[16][128];   // transposed: Bs[k][n]

    const int tid = threadIdx.x;
    const int ty  = tid >> 4;       // 0..15
    const int tx  = tid & 15;       // 0..15
    const int m0  = blockIdx.y << 7;
    const int n0  = blockIdx.x << 7;   // head = blockIdx.x (0..7)

    float acc[8][8];
    #pragma unroll
    for (int i = 0; i < 8; ++i)
        #pragma unroll
        for (int j = 0; j < 8; ++j) acc[i][j] = 0.f;

    const float* Ab = A  + (size_t)m0 * Cc;
    const float* Bbp = Wm + (size_t)n0 * Cc;

    for (int kt = 0; kt < Cc / 16; ++kt) {
        const int k0 = kt * 16;
        __syncthreads();
        #pragma unroll
        for (int s = 0; s < 2; ++s) {
            int idx = tid + (s << 8);       // 0..511
            int r   = idx >> 2;             // 0..127
            int v   = idx & 3;              // float4 slot in row
            float4 fa = *(const float4*)(Ab + (size_t)r * Cc + k0 + 4 * v);
            As[4*v+0][r] = fa.x; As[4*v+1][r] = fa.y;
            As[4*v+2][r] = fa.z; As[4*v+3][r] = fa.w;
            float4 fb = *(const float4*)(Bbp + (size_t)r * Cc + k0 + 4 * v);
            Bs[4*v+0][r] = fb.x; Bs[4*v+1][r] = fb.y;
            Bs[4*v+2][r] = fb.z; Bs[4*v+3][r] = fb.w;
        }
        __syncthreads();
        #pragma unroll
        for (int k = 0; k < 16; ++k) {
            float4 a0 = *(float4*)&As[k][4 * ty];
            float4 a1 = *(float4*)&As[k][64 + 4 * ty];
            float4 b0 = *(float4*)&Bs[k][4 * tx];
            float4 b1 = *(float4*)&Bs[k][64 + 4 * tx];
            float ar[8] = {a0.x, a0.y, a0.z, a0.w, a1.x, a1.y, a1.z, a1.w};
            float br[8] = {b0.x, b0.y, b0.z, b0.w, b1.x, b1.y, b1.z, b1.w};
            #pragma unroll
            for (int i = 0; i < 8; ++i)
                #pragma unroll
                for (int j = 0; j < 8; ++j)
                    acc[i][j] += ar[i] * br[j];
        }
    }

    // epilogue: + bias, scatter into [bh][n][d]
    const int head = blockIdx.x;     // n0 / 128
    float4 bb0 = *(const float4*)(bias + n0 + 4 * tx);
    float4 bb1 = *(const float4*)(bias + n0 + 64 + 4 * tx);
    #pragma unroll
    for (int i = 0; i < 8; ++i) {
        int r = (i < 4) ? (4 * ty + i) : (64 + 4 * ty + (i - 4));
        int m = m0 + r;
        int bbi = m >> 10;            // batch
        int nn  = m & 1023;           // token
        float* dst = g_X + (((size_t)bbi * Hh + head) * Nn + nn) * Dd;
        float4 o0 = make_float4(acc[i][0] + bb0.x, acc[i][1] + bb0.y,
                                acc[i][2] + bb0.z, acc[i][3] + bb0.w);
        float4 o1 = make_float4(acc[i][4] + bb1.x, acc[i][5] + bb1.y,
                                acc[i][6] + bb1.z, acc[i][7] + bb1.w);
        *(float4*)(dst + 4 * tx)      = o0;
        *(float4*)(dst + 64 + 4 * tx) = o1;
    }
}

// ---------------------------------------------------------------------------
// Kernel 2: XM = X @ M  (rows = 262144, K = 128, N = 128)
// Block: 64 rows x 128 cols, BK = 32, 256 threads, 4x8 per thread.
// ---------------------------------------------------------------------------
__global__ void __launch_bounds__(256) k_gemm_xm(const float* __restrict__ Mmat)
{
    __shared__ float As2[64][36];     // padded rows
    __shared__ float Ms[32][128];

    const int tid = threadIdx.x;
    const int ty  = tid >> 4;
    const int tx  = tid & 15;
    const int r0  = blockIdx.x * 64;  // global row (of 262144)

    float acc[4][8];
    #pragma unroll
    for (int i = 0; i < 4; ++i)
        #pragma unroll
        for (int j = 0; j < 8; ++j) acc[i][j] = 0.f;

    for (int kt = 0; kt < 4; ++kt) {
        const int k0 = kt * 32;
        __syncthreads();
        #pragma unroll
        for (int s = 0; s < 2; ++s) {      // X tile: 64 rows x 32 k = 512 f4
            int idx = tid + (s << 8);
            int r = idx >> 3;              // 0..63
            int v = idx & 7;               // 8 f4 per row
            float4 f = *(const float4*)(g_X + (size_t)(r0 + r) * Dd + k0 + 4 * v);
            *(float4*)&As2[r][4 * v] = f;
        }
        #pragma unroll
        for (int s = 0; s < 4; ++s) {      // M tile: 32 x 128 = 1024 f4
            int idx = tid + (s << 8);
            int k = idx >> 5;
            int c4 = (idx & 31) * 4;
            float4 f = *(const float4*)(Mmat + (size_t)(k0 + k) * Dd + c4);
            *(float4*)&Ms[k][c4] = f;
        }
        __syncthreads();
        #pragma unroll 8
        for (int k = 0; k < 32; ++k) {
            float a0 = As2[4 * ty + 0][k];
            float a1 = As2[4 * ty + 1][k];
            float a2 = As2[4 * ty + 2][k];
            float a3 = As2[4 * ty + 3][k];
            float4 b0 = *(float4*)&Ms[k][4 * tx];
            float4 b1 = *(float4*)&Ms[k][64 + 4 * tx];
            float ar[4] = {a0, a1, a2, a3};
            float br[8] = {b0.x, b0.y, b0.z, b0.w, b1.x, b1.y, b1.z, b1.w};
            #pragma unroll
            for (int i = 0; i < 4; ++i)
                #pragma unroll
                for (int j = 0; j < 8; ++j)
                    acc[i][j] += ar[i] * br[j];
        }
    }

    #pragma unroll
    for (int i = 0; i < 4; ++i) {
        float* dst = g_XM + (size_t)(r0 + 4 * ty + i) * Dd;
        float4 o0 = make_float4(acc[i][0], acc[i][1], acc[i][2], acc[i][3]);
        float4 o1 = make_float4(acc[i][4], acc[i][5], acc[i][6], acc[i][7]);
        *(float4*)(dst + 4 * tx)      = o0;
        *(float4*)(dst + 64 + 4 * tx) = o1;
    }
}

// ---------------------------------------------------------------------------
// Kernel 3: flash attention per (bh, q-tile).
//   Q = XM[z] (64 x 128), K = V = X[z] (1024 x 128), no scale, no mask.
// Block = 256 threads; S tile 64x64 (4x4/thread), O tile 64x128 (4x8/thread).
// smem: Qt[128][64] (Q^T), Kt[128][64] (K^T), Vn[64][128], Ps[64][68].
// ---------------------------------------------------------------------------
#define FLASH_SMEM_FLOATS (128*64 + 128*64 + 64*128 + 64*68)
#define FLASH_SMEM_BYTES  (FLASH_SMEM_FLOATS * 4)

__global__ void __launch_bounds__(256) k_flash()
{
    extern __shared__ float sm[];
    float* Qt = sm;                  // [128][64]
    float* Kt = sm + 128 * 64;       // [128][64]
    float* Vn = sm + 2 * 128 * 64;   // [64][128]
    float* Ps = sm + 3 * 128 * 64;   // [64][68]

    const int tid = threadIdx.x;
    const int ty  = tid >> 4;
    const int tx  = tid & 15;
    const int z   = blockIdx.y;          // bh in [0,256)
    const int q0  = blockIdx.x * 64;

    const float* Qg = g_XM + ((size_t)z * Nn + q0) * Dd;
    const float* Xg = g_X  + (size_t)z * Nn * Dd;

    // Load Q transposed
    #pragma unroll
    for (int s = 0; s < 8; ++s) {
        int lin = tid + (s << 8);        // 0..2047
        int r   = lin >> 5;              // 0..63
        int dc  = (lin & 31) * 4;
        float4 f = *(const float4*)(Qg + (size_t)r * Dd + dc);
        Qt[(dc + 0) * 64 + r] = f.x;
        Qt[(dc + 1) * 64 + r] = f.y;
        Qt[(dc + 2) * 64 + r] = f.z;
        Qt[(dc + 3) * 64 + r] = f.w;
    }

    float o[4][8];
    #pragma unroll
    for (int i = 0; i < 4; ++i)
        #pragma unroll
        for (int j = 0; j < 8; ++j) o[i][j] = 0.f;
    float mrow[4], lrow[4];
    #pragma unroll
    for (int i = 0; i < 4; ++i) { mrow[i] = -INFINITY; lrow[i] = 0.f; }

    for (int kt = 0; kt < Nn / 64; ++kt) {
        __syncthreads();
        const float* Kg = Xg + (size_t)kt * 64 * Dd;
        #pragma unroll
        for (int s = 0; s < 8; ++s) {
            int lin = tid + (s << 8);
            int c   = lin >> 5;
            int dc  = (lin & 31) * 4;
            float4 f = *(const float4*)(Kg + (size_t)c * Dd + dc);
            Kt[(dc + 0) * 64 + c] = f.x;
            Kt[(dc + 1) * 64 + c] = f.y;
            Kt[(dc + 2) * 64 + c] = f.z;
            Kt[(dc + 3) * 64 + c] = f.w;
            *(float4*)&Vn[c * 128 + dc] = f;
        }
        __syncthreads();

        // S = Q @ K^T  (inner over d)
        float sacc[4][4];
        #pragma unroll
        for (int i = 0; i < 4; ++i)
            #pragma unroll
            for (int j = 0; j < 4; ++j) sacc[i][j] = 0.f;
        #pragma unroll 16
        for (int k = 0; k < 128; ++k) {
            float4 a  = *(float4*)&Qt[k * 64 + 4 * ty];
            float4 bq = *(float4*)&Kt[k * 64 + 4 * tx];
            float ar[4] = {a.x, a.y, a.z, a.w};
            float br[4] = {bq.x, bq.y, bq.z, bq.w};
            #pragma unroll
            for (int i = 0; i < 4; ++i)
                #pragma unroll
                for (int j = 0; j < 4; ++j)
                    sacc[i][j] += ar[i] * br[j];
        }

        // online softmax update (rows owned by same-ty threads; 16-lane groups)
        #pragma unroll
        for (int i = 0; i < 4; ++i) {
            float mx = fmaxf(fmaxf(sacc[i][0], sacc[i][1]),
                             fmaxf(sacc[i][2], sacc[i][3]));
            #pragma unroll
            for (int off = 1; off < 16; off <<= 1)
                mx = fmaxf(mx, __shfl_xor_sync(0xffffffffu, mx, off));
            float mn = fmaxf(mrow[i], mx);
            float sc = __expf(mrow[i] - mn);
            float p0 = __expf(sacc[i][0] - mn);
            float p1 = __expf(sacc[i][1] - mn);
            float p2 = __expf(sacc[i][2] - mn);
            float p3 = __expf(sacc[i][3] - mn);
            float rs = p0 + p1 + p2 + p3;
            #pragma unroll
            for (int off = 1; off < 16; off <<= 1)
                rs += __shfl_xor_sync(0xffffffffu, rs, off);
            lrow[i] = lrow[i] * sc + rs;
            mrow[i] = mn;
            #pragma unroll
            for (int j = 0; j < 8; ++j) o[i][j] *= sc;
            float4 pv = make_float4(p0, p1, p2, p3);
            *(float4*)&Ps[(4 * ty + i) * 68 + 4 * tx] = pv;
        }
        __syncthreads();

        // O += P @ V   (inner over 64 keys)
        #pragma unroll 8
        for (int kk = 0; kk < 64; ++kk) {
            float a0 = Ps[(4 * ty + 0) * 68 + kk];
            float a1 = Ps[(4 * ty + 1) * 68 + kk];
            float a2 = Ps[(4 * ty + 2) * 68 + kk];
            float a3 = Ps[(4 * ty + 3) * 68 + kk];
            float4 b0 = *(float4*)&Vn[kk * 128 + 4 * tx];
            float4 b1 = *(float4*)&Vn[kk * 128 + 64 + 4 * tx];
            float ar[4] = {a0, a1, a2, a3};
            float br[8] = {b0.x, b0.y, b0.z, b0.w, b1.x, b1.y, b1.z, b1.w};
            #pragma unroll
            for (int i = 0; i < 4; ++i)
                #pragma unroll
                for (int j = 0; j < 8; ++j)
                    o[i][j] += ar[i] * br[j];
        }
    }

    // epilogue: normalize and store
    float* Og = g_O + ((size_t)z * Nn + q0) * Dd;
    #pragma unroll
    for (int i = 0; i < 4; ++i) {
        float inv = 1.f / lrow[i];
        float4 r0v = make_float4(o[i][0] * inv, o[i][1] * inv,
                                 o[i][2] * inv, o[i][3] * inv);
        float4 r1v = make_float4(o[i][4] * inv, o[i][5] * inv,
                                 o[i][6] * inv, o[i][7] * inv);
        float* dst = Og + (size_t)(4 * ty + i) * Dd;
        *(float4*)(dst + 4 * tx)      = r0v;
        *(float4*)(dst + 64 + 4 * tx) = r1v;
    }
}

// ---------------------------------------------------------------------------
// Kernel 4: gather heads -> [b, n, c] row, LayerNorm over c, exact GELU.
// One block per (b, n) row; 256 threads x 4 contiguous c each.
// ---------------------------------------------------------------------------
__global__ void __launch_bounds__(256) k_ln_gelu(const float* __restrict__ gamma,
                                                 const float* __restrict__ beta,
                                                 float* __restrict__ out)
{
    const int row = blockIdx.x;        // 0..32767
    const int bbi = row >> 10;
    const int nn  = row & 1023;
    const int tid = threadIdx.x;
    const int c0  = tid * 4;
    const int head = c0 >> 7;
    const int dd   = c0 & 127;

    const float* src = g_O + (((size_t)bbi * Hh + head) * Nn + nn) * Dd + dd;
    float4 v = *(const float4*)src;

    float s = v.x + v.y + v.z + v.w;
    float q = v.x * v.x + v.y * v.y + v.z * v.z + v.w * v.w;
    #pragma unroll
    for (int off = 16; off >= 1; off >>= 1) {
        s += __shfl_xor_sync(0xffffffffu, s, off);
        q += __shfl_xor_sync(0xffffffffu, q, off);
    }
    __shared__ float ss[8], sq[8];
    int w  = tid >> 5;
    int ln = tid & 31;
    if (ln == 0) { ss[w] = s; sq[w] = q; }
    __syncthreads();
    float st = 0.f, qt = 0.f;
    #pragma unroll
    for (int k = 0; k < 8; ++k) { st += ss[k]; qt += sq[k]; }

    const float mean = st * (1.f / (float)Cc);
    const float var  = qt * (1.f / (float)Cc) - mean * mean;
    const float rstd = rsqrtf(var + 1e-5f);

    float4 g  = *(const float4*)(gamma + c0);
    float4 be = *(const float4*)(beta  + c0);

    float y0 = (v.x - mean) * rstd * g.x + be.x;
    float y1 = (v.y - mean) * rstd * g.y + be.y;
    float y2 = (v.z - mean) * rstd * g.z + be.z;
    float y3 = (v.w - mean) * rstd * g.w + be.w;

    const float kInvSqrt2 = 0.70710678118654752440f;
    float4 r;
    r.x = 0.5f * y0 * (1.f + erff(y0 * kInvSqrt2));
    r.y = 0.5f * y1 * (1.f + erff(y1 * kInvSqrt2));
    r.z = 0.5f * y2 * (1.f + erff(y2 * kInvSqrt2));
    r.w = 0.5f * y3 * (1.f + erff(y3 * kInvSqrt2));

    *(float4*)(out + (size_t)row * Cc + c0) = r;
}

// ---------------------------------------------------------------------------
extern "C" void kernel_launch(void* const* d_in, const int* in_sizes, int n_in,
                              void* d_out, int out_size)
{
    const float* h     = (const float*)d_in[0];
    const float* W_w   = (const float*)d_in[1];
    const float* W_b   = (const float*)d_in[2];
    const float* Mmat  = (const float*)d_in[3];
    const float* gamma = (const float*)d_in[4];
    const float* beta  = (const float*)d_in[5];
    float* out = (float*)d_out;

    // opt-in to >48KB dynamic smem for the flash kernel (idempotent, host-side)
    cudaFuncSetAttribute(k_flash, cudaFuncAttributeMaxDynamicSharedMemorySize,
                         FLASH_SMEM_BYTES);

    // 1) X = h @ W^T + b   -> g_X [bh][n][d]
    k_gemm_xw<<<dim3(Cc / 128, MROWS / 128), 256>>>(h, W_w, W_b);

    // 2) XM = X @ M        -> g_XM
    k_gemm_xm<<<(BHn * Nn) / 64, 256>>>(Mmat);

    // 3) flash attention   -> g_O
    k_flash<<<dim3(Nn / 64, BHn), 256, FLASH_SMEM_BYTES>>>();

    // 4) LayerNorm + GELU  -> out [b, n, c]
    k_ln_gelu<<<MROWS, 256>>>(gamma, beta, out);
}

// round 5
// speedup vs baseline: 2.0095x; 2.0095x over previous
#include <cuda_runtime.h>
#include <stdint.h>
#include <math.h>

// Fixed shapes for GraphAttentionLayer_18021682774974
#define Bb  32
#define Nn  1024
#define Cc  1024
#define Hh  8
#define Dd  128
#define BHn 256                      // Bb*Hh
#define MROWS (Bb * Nn)              // 32768

// Scratch (device globals; no cudaMalloc allowed)
__device__ float g_X [BHn * Nn * Dd];          // X   [z][n][d]
__device__ float g_XT[BHn * Nn * Dd];          // X^T [z][d][n]
__device__ float g_XM[BHn * Nn * Dd];          // X@M [z][n][d]
__device__ float g_O [BHn * Nn * Dd];          // attention out
__device__ float g_P [(size_t)BHn * Nn * Nn];  // exp(S)  (1 GB)
__device__ float g_L [BHn * Nn * 8];           // row-sum partials per n-tile

__device__ __forceinline__ uint32_t f2tf32(float f) {
    uint32_t r;
    asm("cvt.rna.tf32.f32 %0, %1;" : "=r"(r) : "f"(f));
    return r;
}
// hi/lo split: hi = tf32(x), lo = tf32(x - hi)
__device__ __forceinline__ void split_tf32(float x, uint32_t& hi, uint32_t& lo) {
    hi = f2tf32(x);
    lo = f2tf32(x - __uint_as_float(hi));
}

#define MMA_TF32(d, a, b)                                                     \
    asm volatile("mma.sync.aligned.m16n8k8.row.col.f32.tf32.tf32.f32 "        \
                 "{%0,%1,%2,%3}, {%4,%5,%6,%7}, {%8,%9}, {%0,%1,%2,%3};"      \
                 : "+f"((d)[0]), "+f"((d)[1]), "+f"((d)[2]), "+f"((d)[3])     \
                 : "r"((a)[0]), "r"((a)[1]), "r"((a)[2]), "r"((a)[3]),        \
                   "r"((b)[0]), "r"((b)[1]))

// smem layout (floats):
//   A_hi bufs [2][256*20] at 0     / 5120
//   A_lo bufs [2][256*20] at 10240 / 15360
//   B_hi bufs [2][128*20] at 20480 / 23040
//   B_lo bufs [2][128*20] at 25600 / 28160
// Total 30720 floats = 122880 B (modes w/o split leave lo regions unused).
#define APITCH 20
#define ABUF   5120
#define ALO    10240
#define BHI    20480
#define BBUF   2560
#define BLO    25600
#define SMEM_DYN 122880

// ---------------------------------------------------------------------------
// Unified mma.sync tf32 GEMM. D[256 x 128] = A @ B^T (B stored [n][k]).
// MODE 0: X = h @ W^T + bias          (K=1024) grid (8 heads, 128 mtiles)  3xTF32
// MODE 1: XM = X @ M                  (K=128)  grid (1024)                 3xTF32
// MODE 2: P = exp(XM @ X^T), lpart    (K=128)  grid (8 nt, 4 mt, 256 z)    3xTF32
// MODE 3: O = (P @ V) / l             (K=1024) grid (4 mt, 256 z)          1xTF32
// ---------------------------------------------------------------------------
template<int MODE>
__global__ void __launch_bounds__(256, 1) k_mma(const float* __restrict__ P0,
                                                const float* __restrict__ P1,
                                                const float* __restrict__ P2)
{
    extern __shared__ float smf[];
    uint32_t* smU = (uint32_t*)smf;
    constexpr bool SPLIT = (MODE != 3);

    const int tid  = threadIdx.x;
    const int wid  = tid >> 5, lane = tid & 31;
    const int wm   = wid >> 1, wn = wid & 1;
    const int g    = lane >> 2, t = lane & 3;

    int m0 = 0, n0 = 0; size_t z = 0;
    const float* Asrc = nullptr; const float* Bsrc = nullptr;
    int Ast = 0, Bst = 0;
    if (MODE == 0) {
        m0 = blockIdx.y * 256; n0 = blockIdx.x * 128;
        Asrc = P0 + (size_t)m0 * Cc; Ast = Cc;
        Bsrc = P1 + (size_t)n0 * Cc; Bst = Cc;
    } else if (MODE == 1) {
        m0 = blockIdx.x * 256;
        Asrc = g_X + (size_t)m0 * Dd; Ast = Dd;   // B = M^T (special load)
    } else if (MODE == 2) {
        z = blockIdx.z; m0 = blockIdx.y * 256; n0 = blockIdx.x * 128;
        Asrc = g_XM + (z * Nn + m0) * (size_t)Dd; Ast = Dd;
        Bsrc = g_X  + (z * Nn + n0) * (size_t)Dd; Bst = Dd;
    } else {
        z = blockIdx.y; m0 = blockIdx.x * 256;
        Asrc = g_P  + (z * Nn + m0) * (size_t)Nn; Ast = Nn;
        Bsrc = g_XT + z * (size_t)(Dd * Nn);      Bst = Nn;
    }

    constexpr int NC = (MODE == 0 || MODE == 3) ? 64 : 8;   // K chunks of 16

    float acc[4][8][4];
    #pragma unroll
    for (int a = 0; a < 4; ++a)
        #pragma unroll
        for (int b = 0; b < 8; ++b)
            #pragma unroll
            for (int cix = 0; cix < 4; ++cix) acc[a][b][cix] = 0.f;

    // ---- store helpers (write hi tile, and lo tile when SPLIT) ----
    auto storeA = [&](int bufsel, int idx4, float4 f) {
        uint32_t h0,l0,h1,l1,h2,l2,h3,l3;
        split_tf32(f.x, h0, l0); split_tf32(f.y, h1, l1);
        split_tf32(f.z, h2, l2); split_tf32(f.w, h3, l3);
        *(uint4*)&smU[bufsel * ABUF + idx4] = make_uint4(h0, h1, h2, h3);
        if (SPLIT)
            *(uint4*)&smU[ALO + bufsel * ABUF + idx4] = make_uint4(l0, l1, l2, l3);
    };
    auto storeB = [&](int bufsel, int idx4, float4 f) {
        uint32_t h0,l0,h1,l1,h2,l2,h3,l3;
        split_tf32(f.x, h0, l0); split_tf32(f.y, h1, l1);
        split_tf32(f.z, h2, l2); split_tf32(f.w, h3, l3);
        *(uint4*)&smU[BHI + bufsel * BBUF + idx4] = make_uint4(h0, h1, h2, h3);
        if (SPLIT)
            *(uint4*)&smU[BLO + bufsel * BBUF + idx4] = make_uint4(l0, l1, l2, l3);
    };
    auto storeB1 = [&](int bufsel, int idx, float v) {   // scalar (mode 1 transpose)
        uint32_t h, l;
        split_tf32(v, h, l);
        smU[BHI + bufsel * BBUF + idx] = h;
        smU[BLO + bufsel * BBUF + idx] = l;
    };

    // ---- initial load: chunk 0 -> buf 0 ----
    {
        #pragma unroll
        for (int i = 0; i < 4; ++i) {
            int id = tid + (i << 8), r = id >> 2, c4 = (id & 3) << 2;
            float4 f = *(const float4*)(Asrc + (size_t)r * Ast + c4);
            storeA(0, r * APITCH + c4, f);
        }
        if (MODE == 1) {
            int kk = tid >> 4, nb = (tid & 15) << 3;
            float4 f0 = *(const float4*)(P1 + (size_t)kk * Dd + nb);
            float4 f1 = *(const float4*)(P1 + (size_t)kk * Dd + nb + 4);
            storeB1(0, (nb+0)*APITCH + kk, f0.x);
            storeB1(0, (nb+1)*APITCH + kk, f0.y);
            storeB1(0, (nb+2)*APITCH + kk, f0.z);
            storeB1(0, (nb+3)*APITCH + kk, f0.w);
            storeB1(0, (nb+4)*APITCH + kk, f1.x);
            storeB1(0, (nb+5)*APITCH + kk, f1.y);
            storeB1(0, (nb+6)*APITCH + kk, f1.z);
            storeB1(0, (nb+7)*APITCH + kk, f1.w);
        } else {
            #pragma unroll
            for (int i = 0; i < 2; ++i) {
                int id = tid + (i << 8), r = id >> 2, c4 = (id & 3) << 2;
                float4 f = *(const float4*)(Bsrc + (size_t)r * Bst + c4);
                storeB(0, r * APITCH + c4, f);
            }
        }
    }
    __syncthreads();

    // ---- main loop ----
    for (int c = 0; c < NC; ++c) {
        const int cur = c & 1;
        const uint32_t* Ah = smU + cur * ABUF;
        const uint32_t* Al = smU + ALO + cur * ABUF;
        const uint32_t* Bh = smU + BHI + cur * BBUF;
        const uint32_t* Bl = smU + BLO + cur * BBUF;

        // prefetch next chunk into registers
        float4 pa[4]; float4 pb0, pb1;
        const bool pf = (c + 1 < NC);
        const int k1 = (c + 1) << 4;
        if (pf) {
            #pragma unroll
            for (int i = 0; i < 4; ++i) {
                int id = tid + (i << 8), r = id >> 2, c4 = (id & 3) << 2;
                pa[i] = *(const float4*)(Asrc + (size_t)r * Ast + k1 + c4);
            }
            if (MODE == 1) {
                int kk = tid >> 4, nb = (tid & 15) << 3;
                pb0 = *(const float4*)(P1 + (size_t)(k1 + kk) * Dd + nb);
                pb1 = *(const float4*)(P1 + (size_t)(k1 + kk) * Dd + nb + 4);
            } else {
                int r0 = tid >> 2,        c40 = (tid & 3) << 2;
                int r1 = (tid + 256) >> 2;
                pb0 = *(const float4*)(Bsrc + (size_t)r0 * Bst + k1 + c40);
                pb1 = *(const float4*)(Bsrc + (size_t)r1 * Bst + k1 + c40);
            }
        }

        // compute 2 k-steps of 8
        #pragma unroll
        for (int ks = 0; ks < 2; ++ks) {
            uint32_t af[4][4], bf[8][2];
            #pragma unroll
            for (int mf = 0; mf < 4; ++mf) {
                int base = (wm * 64 + mf * 16 + g) * APITCH + ks * 8 + t;
                af[mf][0] = Ah[base];
                af[mf][1] = Ah[base + 8 * APITCH];
                af[mf][2] = Ah[base + 4];
                af[mf][3] = Ah[base + 8 * APITCH + 4];
            }
            #pragma unroll
            for (int nf = 0; nf < 8; ++nf) {
                int base = (wn * 64 + nf * 8 + g) * APITCH + ks * 8 + t;
                bf[nf][0] = Bh[base];
                bf[nf][1] = Bh[base + 4];
            }
            // hi x hi
            #pragma unroll
            for (int mf = 0; mf < 4; ++mf)
                #pragma unroll
                for (int nf = 0; nf < 8; ++nf)
                    MMA_TF32(acc[mf][nf], af[mf], bf[nf]);

            if (SPLIT) {
                // hi_A x lo_B
                uint32_t xf[8][2];
                #pragma unroll
                for (int nf = 0; nf < 8; ++nf) {
                    int base = (wn * 64 + nf * 8 + g) * APITCH + ks * 8 + t;
                    xf[nf][0] = Bl[base];
                    xf[nf][1] = Bl[base + 4];
                }
                #pragma unroll
                for (int mf = 0; mf < 4; ++mf)
                    #pragma unroll
                    for (int nf = 0; nf < 8; ++nf)
                        MMA_TF32(acc[mf][nf], af[mf], xf[nf]);
                // lo_A x hi_B
                uint32_t al[4][4];
                #pragma unroll
                for (int mf = 0; mf < 4; ++mf) {
                    int base = (wm * 64 + mf * 16 + g) * APITCH + ks * 8 + t;
                    al[mf][0] = Al[base];
                    al[mf][1] = Al[base + 8 * APITCH];
                    al[mf][2] = Al[base + 4];
                    al[mf][3] = Al[base + 8 * APITCH + 4];
                }
                #pragma unroll
                for (int mf = 0; mf < 4; ++mf)
                    #pragma unroll
                    for (int nf = 0; nf < 8; ++nf)
                        MMA_TF32(acc[mf][nf], al[mf], bf[nf]);
            }
        }
        __syncthreads();

        if (pf) {
            const int nxt = (c + 1) & 1;
            #pragma unroll
            for (int i = 0; i < 4; ++i) {
                int id = tid + (i << 8), r = id >> 2, c4 = (id & 3) << 2;
                storeA(nxt, r * APITCH + c4, pa[i]);
            }
            if (MODE == 1) {
                int kk = tid >> 4, nb = (tid & 15) << 3;
                storeB1(nxt, (nb+0)*APITCH + kk, pb0.x);
                storeB1(nxt, (nb+1)*APITCH + kk, pb0.y);
                storeB1(nxt, (nb+2)*APITCH + kk, pb0.z);
                storeB1(nxt, (nb+3)*APITCH + kk, pb0.w);
                storeB1(nxt, (nb+4)*APITCH + kk, pb1.x);
                storeB1(nxt, (nb+5)*APITCH + kk, pb1.y);
                storeB1(nxt, (nb+6)*APITCH + kk, pb1.z);
                storeB1(nxt, (nb+7)*APITCH + kk, pb1.w);
            } else {
                int r0 = tid >> 2,        c40 = (tid & 3) << 2;
                int r1 = (tid + 256) >> 2;
                storeB(nxt, r0 * APITCH + c40, pb0);
                storeB(nxt, r1 * APITCH + c40, pb1);
            }
            __syncthreads();
        }
    }
    __syncthreads();

    // ---- epilogue ----
    // thread owns rows rm = wm*64 + mf*16 + g + 8h, cols cn = wn*64 + nf*8 + 2t
    if (MODE == 0) {
        const int head = blockIdx.x;
        #pragma unroll
        for (int mf = 0; mf < 4; ++mf)
            #pragma unroll
            for (int hh = 0; hh < 2; ++hh) {
                int m = m0 + wm * 64 + mf * 16 + g + 8 * hh;
                int bidx = m >> 10, tok = m & 1023;
                float* dst = g_X + (((size_t)bidx * Hh + head) * Nn + tok) * Dd;
                #pragma unroll
                for (int nf = 0; nf < 8; ++nf) {
                    int col = wn * 64 + nf * 8 + 2 * t;
                    float b0 = P2[n0 + col], b1 = P2[n0 + col + 1];
                    *(float2*)(dst + col) =
                        make_float2(acc[mf][nf][2*hh+0] + b0,
                                    acc[mf][nf][2*hh+1] + b1);
                }
            }
    } else if (MODE == 1) {
        #pragma unroll
        for (int mf = 0; mf < 4; ++mf)
            #pragma unroll
            for (int hh = 0; hh < 2; ++hh) {
                int m = m0 + wm * 64 + mf * 16 + g + 8 * hh;
                float* dst = g_XM + (size_t)m * Dd;
                #pragma unroll
                for (int nf = 0; nf < 8; ++nf) {
                    int col = wn * 64 + nf * 8 + 2 * t;
                    *(float2*)(dst + col) =
                        make_float2(acc[mf][nf][2*hh+0], acc[mf][nf][2*hh+1]);
                }
            }
    } else if (MODE == 2) {
        float rsum[4][2];
        #pragma unroll
        for (int mf = 0; mf < 4; ++mf) { rsum[mf][0] = 0.f; rsum[mf][1] = 0.f; }
        #pragma unroll
        for (int mf = 0; mf < 4; ++mf)
            #pragma unroll
            for (int hh = 0; hh < 2; ++hh) {
                int rm = wm * 64 + mf * 16 + g + 8 * hh;
                float* dst = g_P + (z * Nn + m0 + rm) * (size_t)Nn + n0;
                #pragma unroll
                for (int nf = 0; nf < 8; ++nf) {
                    int col = wn * 64 + nf * 8 + 2 * t;
                    float e0 = __expf(acc[mf][nf][2*hh+0]);
                    float e1 = __expf(acc[mf][nf][2*hh+1]);
                    rsum[mf][hh] += e0 + e1;
                    *(float2*)(dst + col) = make_float2(e0, e1);
                }
            }
        // reduce across quad lanes (t bits), then across wn via smem
        float* ssum = smf;  // aliases A buf (compute done)
        #pragma unroll
        for (int mf = 0; mf < 4; ++mf)
            #pragma unroll
            for (int hh = 0; hh < 2; ++hh) {
                float s = rsum[mf][hh];
                s += __shfl_xor_sync(0xffffffffu, s, 1);
                s += __shfl_xor_sync(0xffffffffu, s, 2);
                if (t == 0)
                    ssum[(wm * 64 + mf * 16 + g + 8 * hh) * 2 + wn] = s;
            }
        __syncthreads();
        {
            float l = ssum[tid * 2] + ssum[tid * 2 + 1];
            g_L[(z * Nn + m0 + tid) * 8 + blockIdx.x] = l;
        }
    } else {  // MODE 3
        #pragma unroll
        for (int mf = 0; mf < 4; ++mf)
            #pragma unroll
            for (int hh = 0; hh < 2; ++hh) {
                size_t row = z * Nn + m0 + wm * 64 + mf * 16 + g + 8 * hh;
                const float* lp = g_L + row * 8;
                float l = ((lp[0] + lp[1]) + (lp[2] + lp[3]))
                        + ((lp[4] + lp[5]) + (lp[6] + lp[7]));
                float inv = 1.f / l;
                float* dst = g_O + row * (size_t)Dd;
                #pragma unroll
                for (int nf = 0; nf < 8; ++nf) {
                    int col = wn * 64 + nf * 8 + 2 * t;
                    *(float2*)(dst + col) =
                        make_float2(acc[mf][nf][2*hh+0] * inv,
                                    acc[mf][nf][2*hh+1] * inv);
                }
            }
    }
}

// ---------------------------------------------------------------------------
// Transpose: g_XT[z][d][n] = g_X[z][n][d]
// ---------------------------------------------------------------------------
__global__ void __launch_bounds__(256) k_transpose()
{
    __shared__ float tsm[32][33];
    const int z  = blockIdx.z;
    const int d0 = blockIdx.y << 5;
    const int nb = blockIdx.x << 5;
    const int lx = threadIdx.x, ly = threadIdx.y;
    const float* src = g_X + (size_t)z * Nn * Dd;
    #pragma unroll
    for (int i = 0; i < 32; i += 8)
        tsm[ly + i][lx] = src[(size_t)(nb + ly + i) * Dd + d0 + lx];
    __syncthreads();
    float* dst = g_XT + (size_t)z * Dd * Nn;
    #pragma unroll
    for (int i = 0; i < 32; i += 8)
        dst[(size_t)(d0 + ly + i) * Nn + nb + lx] = tsm[lx][ly + i];
}

// ---------------------------------------------------------------------------
// LayerNorm + exact GELU over c (gather heads)
// ---------------------------------------------------------------------------
__global__ void __launch_bounds__(256) k_ln_gelu(const float* __restrict__ gamma,
                                                 const float* __restrict__ beta,
                                                 float* __restrict__ out)
{
    const int row = blockIdx.x;
    const int bbi = row >> 10, nn = row & 1023;
    const int tid = threadIdx.x;
    const int c0 = tid * 4, head = c0 >> 7, dd = c0 & 127;

    const float* src = g_O + (((size_t)bbi * Hh + head) * Nn + nn) * Dd + dd;
    float4 v = *(const float4*)src;

    float s = v.x + v.y + v.z + v.w;
    float q = v.x*v.x + v.y*v.y + v.z*v.z + v.w*v.w;
    #pragma unroll
    for (int off = 16; off >= 1; off >>= 1) {
        s += __shfl_xor_sync(0xffffffffu, s, off);
        q += __shfl_xor_sync(0xffffffffu, q, off);
    }
    __shared__ float ss[8], sq[8];
    if ((tid & 31) == 0) { ss[tid >> 5] = s; sq[tid >> 5] = q; }
    __syncthreads();
    float st = 0.f, qt = 0.f;
    #pragma unroll
    for (int k = 0; k < 8; ++k) { st += ss[k]; qt += sq[k]; }

    const float mean = st * (1.f / (float)Cc);
    const float var  = qt * (1.f / (float)Cc) - mean * mean;
    const float rstd = rsqrtf(var + 1e-5f);

    float4 gm = *(const float4*)(gamma + c0);
    float4 be = *(const float4*)(beta + c0);
    float y0 = (v.x - mean) * rstd * gm.x + be.x;
    float y1 = (v.y - mean) * rstd * gm.y + be.y;
    float y2 = (v.z - mean) * rstd * gm.z + be.z;
    float y3 = (v.w - mean) * rstd * gm.w + be.w;

    const float k2 = 0.70710678118654752440f;
    float4 rr;
    rr.x = 0.5f * y0 * (1.f + erff(y0 * k2));
    rr.y = 0.5f * y1 * (1.f + erff(y1 * k2));
    rr.z = 0.5f * y2 * (1.f + erff(y2 * k2));
    rr.w = 0.5f * y3 * (1.f + erff(y3 * k2));
    *(float4*)(out + (size_t)row * Cc + c0) = rr;
}

// ---------------------------------------------------------------------------
extern "C" void kernel_launch(void* const* d_in, const int* in_sizes, int n_in,
                              void* d_out, int out_size)
{
    const float* h     = (const float*)d_in[0];
    const float* W_w   = (const float*)d_in[1];
    const float* W_b   = (const float*)d_in[2];
    const float* Mmat  = (const float*)d_in[3];
    const float* gamma = (const float*)d_in[4];
    const float* beta  = (const float*)d_in[5];
    float* out = (float*)d_out;

    cudaFuncSetAttribute(k_mma<0>, cudaFuncAttributeMaxDynamicSharedMemorySize, SMEM_DYN);
    cudaFuncSetAttribute(k_mma<1>, cudaFuncAttributeMaxDynamicSharedMemorySize, SMEM_DYN);
    cudaFuncSetAttribute(k_mma<2>, cudaFuncAttributeMaxDynamicSharedMemorySize, SMEM_DYN);
    cudaFuncSetAttribute(k_mma<3>, cudaFuncAttributeMaxDynamicSharedMemorySize, SMEM_DYN);

    // 1) X = h @ W^T + b               -> g_X [z][n][d]          (3xTF32)
    k_mma<0><<<dim3(Hh, MROWS / 256), 256, SMEM_DYN>>>(h, W_w, W_b);
    // 2) X^T                           -> g_XT [z][d][n]
    k_transpose<<<dim3(Nn / 32, Dd / 32, BHn), dim3(32, 8)>>>();
    // 3) XM = X @ M                    -> g_XM                   (3xTF32)
    k_mma<1><<<dim3((BHn * Nn) / 256), 256, SMEM_DYN>>>(nullptr, Mmat, nullptr);
    // 4) P = exp(XM @ X^T), lpart      -> g_P, g_L               (3xTF32)
    k_mma<2><<<dim3(Nn / 128, Nn / 256, BHn), 256, SMEM_DYN>>>(nullptr, nullptr, nullptr);
    // 5) O = (P @ V) / l               -> g_O                    (1xTF32)
    k_mma<3><<<dim3(Nn / 256, BHn), 256, SMEM_DYN>>>(nullptr, nullptr, nullptr);
    // 6) LayerNorm + GELU              -> out
    k_ln_gelu<<<MROWS, 256>>>(gamma, beta, out);
}

// round 6
// speedup vs baseline: 2.9704x; 1.4782x over previous
#include <cuda_runtime.h>
#include <cuda_fp16.h>
#include <stdint.h>
#include <math.h>

// Fixed shapes for GraphAttentionLayer_18021682774974
#define Bb  32
#define Nn  1024
#define Cc  1024
#define Hh  8
#define Dd  128
#define BHn 256                      // Bb*Hh
#define MROWS (Bb * Nn)              // 32768

// Scratch (device globals; no cudaMalloc allowed)
__device__ float g_X [BHn * Nn * Dd];          // X   [z][n][d]
__device__ float g_XT[BHn * Nn * Dd];          // X^T [z][d][n]
__device__ float g_XM[BHn * Nn * Dd];          // X@M [z][n][d]
__device__ float g_O [BHn * Nn * Dd];          // attention out
__device__ float g_P [(size_t)BHn * Nn * Nn];  // exp(S)  (1 GB)
__device__ float g_L [BHn * Nn * 8];           // row-sum partials per n-tile

// ---------------------------------------------------------------------------
// helpers
// ---------------------------------------------------------------------------
__device__ __forceinline__ uint32_t f2tf32(float f) {
    uint32_t r;
    asm("cvt.rna.tf32.f32 %0, %1;" : "=r"(r) : "f"(f));
    return r;
}
// fp16 hi/lo split of a pair -> packed half2 words
__device__ __forceinline__ void split2(float a, float b, uint32_t& hi, uint32_t& lo) {
    __half ha = __float2half_rn(a), hb = __float2half_rn(b);
    float ra = a - __half2float(ha), rb = b - __half2float(hb);
    __half2 H = __halves2half2(ha, hb);
    __half2 L = __floats2half2_rn(ra, rb);
    hi = *(uint32_t*)&H;
    lo = *(uint32_t*)&L;
}

#define MMA_TF32(d, a, b)                                                     \
    asm volatile("mma.sync.aligned.m16n8k8.row.col.f32.tf32.tf32.f32 "        \
                 "{%0,%1,%2,%3}, {%4,%5,%6,%7}, {%8,%9}, {%0,%1,%2,%3};"      \
                 : "+f"((d)[0]), "+f"((d)[1]), "+f"((d)[2]), "+f"((d)[3])     \
                 : "r"((a)[0]), "r"((a)[1]), "r"((a)[2]), "r"((a)[3]),        \
                   "r"((b)[0]), "r"((b)[1]))

#define MMA_F16(d, a, b)                                                      \
    asm volatile("mma.sync.aligned.m16n8k16.row.col.f32.f16.f16.f32 "         \
                 "{%0,%1,%2,%3}, {%4,%5,%6,%7}, {%8,%9}, {%0,%1,%2,%3};"      \
                 : "+f"((d)[0]), "+f"((d)[1]), "+f"((d)[2]), "+f"((d)[3])     \
                 : "r"((a)[0]), "r"((a)[1]), "r"((a)[2]), "r"((a)[3]),        \
                   "r"((b)[0]), "r"((b)[1]))

// ===========================================================================
// FP16 3-term split GEMM (modes 0,1,2).  D[256x128] = A @ B^T, fp32 accum.
// smem words (uint32): AH[2][2048]@0, AL[2][2048]@4096,
//                      BH[2][1024]@8192, BL[2][1024]@10240.  48 KB total.
// word (row, w) at row*8 + (w ^ (row&7))  -> conflict-free fragment loads.
// MODE 0: X = h @ W^T + bias        (K=1024) grid (8 heads, 128 mtiles)
// MODE 1: XM = X @ M                (K=128)  grid (1024)
// MODE 2: P = exp(XM @ X^T), lpart  (K=128)  grid (8 nt, 4 mt, 256 z)
// ===========================================================================
#define AH0 0
#define AL0 4096
#define BH0 8192
#define BL0 10240
#define SMEM_F16 49152

template<int MODE>
__global__ void __launch_bounds__(256, 1) k_f16(const float* __restrict__ P0,
                                                const float* __restrict__ P1,
                                                const float* __restrict__ P2)
{
    extern __shared__ uint32_t smw[];

    const int tid  = threadIdx.x;
    const int wid  = tid >> 5, lane = tid & 31;
    const int wm   = wid >> 1, wn = wid & 1;
    const int g    = lane >> 2, t = lane & 3;

    int m0 = 0, n0 = 0; size_t z = 0;
    const float* Asrc = nullptr; const float* Bsrc = nullptr;
    int Ast = 0, Bst = 0;
    if (MODE == 0) {
        m0 = blockIdx.y * 256; n0 = blockIdx.x * 128;
        Asrc = P0 + (size_t)m0 * Cc; Ast = Cc;
        Bsrc = P1 + (size_t)n0 * Cc; Bst = Cc;
    } else if (MODE == 1) {
        m0 = blockIdx.x * 256;
        Asrc = g_X + (size_t)m0 * Dd; Ast = Dd;   // B = M^T (special load)
    } else {
        z = blockIdx.z; m0 = blockIdx.y * 256; n0 = blockIdx.x * 128;
        Asrc = g_XM + (z * Nn + m0) * (size_t)Dd; Ast = Dd;
        Bsrc = g_X  + (z * Nn + n0) * (size_t)Dd; Bst = Dd;
    }
    constexpr int NC = (MODE == 0) ? 64 : 8;   // K chunks of 16

    float acc[4][8][4];
    #pragma unroll
    for (int a = 0; a < 4; ++a)
        #pragma unroll
        for (int b = 0; b < 8; ++b)
            #pragma unroll
            for (int cix = 0; cix < 4; ++cix) acc[a][b][cix] = 0.f;

    auto stA = [&](int buf, int r, int w, uint32_t hi, uint32_t lo) {
        int idx = buf * 2048 + r * 8 + (w ^ (r & 7));
        smw[AH0 + idx] = hi;
        smw[AL0 + idx] = lo;
    };
    auto stB = [&](int buf, int r, int w, uint32_t hi, uint32_t lo) {
        int idx = buf * 1024 + r * 8 + (w ^ (r & 7));
        smw[BH0 + idx] = hi;
        smw[BL0 + idx] = lo;
    };
    auto putA4 = [&](int buf, int r, int c4, float4 f) {
        uint32_t h0, l0, h1, l1;
        split2(f.x, f.y, h0, l0);
        split2(f.z, f.w, h1, l1);
        stA(buf, r, (c4 >> 1),     h0, l0);
        stA(buf, r, (c4 >> 1) + 1, h1, l1);
    };
    auto putB4 = [&](int buf, int r, int c4, float4 f) {
        uint32_t h0, l0, h1, l1;
        split2(f.x, f.y, h0, l0);
        split2(f.z, f.w, h1, l1);
        stB(buf, r, (c4 >> 1),     h0, l0);
        stB(buf, r, (c4 >> 1) + 1, h1, l1);
    };
    // mode-1 transposed B store: word [n][kp] = (M[2kp][n], M[2kp+1][n])
    auto putB_T = [&](int buf, int kp, int nb, float4 f0, float4 f1) {
        uint32_t h, l;
        split2(f0.x, f1.x, h, l); stB(buf, nb + 0, kp, h, l);
        split2(f0.y, f1.y, h, l); stB(buf, nb + 1, kp, h, l);
        split2(f0.z, f1.z, h, l); stB(buf, nb + 2, kp, h, l);
        split2(f0.w, f1.w, h, l); stB(buf, nb + 3, kp, h, l);
    };

    // ---- initial load: chunk 0 -> buf 0 ----
    {
        #pragma unroll
        for (int i = 0; i < 4; ++i) {
            int id = tid + (i << 8), r = id >> 2, c4 = (id & 3) << 2;
            float4 f = *(const float4*)(Asrc + (size_t)r * Ast + c4);
            putA4(0, r, c4, f);
        }
        if (MODE == 1) {
            int kp = tid >> 5, nb = (tid & 31) << 2;
            float4 f0 = *(const float4*)(P1 + (size_t)(2 * kp)     * Dd + nb);
            float4 f1 = *(const float4*)(P1 + (size_t)(2 * kp + 1) * Dd + nb);
            putB_T(0, kp, nb, f0, f1);
        } else {
            #pragma unroll
            for (int i = 0; i < 2; ++i) {
                int id = tid + (i << 8), r = id >> 2, c4 = (id & 3) << 2;
                float4 f = *(const float4*)(Bsrc + (size_t)r * Bst + c4);
                putB4(0, r, c4, f);
            }
        }
    }
    __syncthreads();

    // ---- main loop ----
    for (int c = 0; c < NC; ++c) {
        const int cur = c & 1;
        const uint32_t* AH = smw + AH0 + cur * 2048;
        const uint32_t* AL = smw + AL0 + cur * 2048;
        const uint32_t* BH = smw + BH0 + cur * 1024;
        const uint32_t* BL = smw + BL0 + cur * 1024;

        // prefetch next chunk into registers
        float4 pa[4]; float4 pb0, pb1;
        const bool pf = (c + 1 < NC);
        const int k1 = (c + 1) << 4;
        if (pf) {
            #pragma unroll
            for (int i = 0; i < 4; ++i) {
                int id = tid + (i << 8), r = id >> 2, c4 = (id & 3) << 2;
                pa[i] = *(const float4*)(Asrc + (size_t)r * Ast + k1 + c4);
            }
            if (MODE == 1) {
                int kp = tid >> 5, nb = (tid & 31) << 2;
                pb0 = *(const float4*)(P1 + (size_t)(k1 + 2 * kp)     * Dd + nb);
                pb1 = *(const float4*)(P1 + (size_t)(k1 + 2 * kp + 1) * Dd + nb);
            } else {
                int r0 = tid >> 2,         c40 = (tid & 3) << 2;
                int r1 = (tid + 256) >> 2;
                pb0 = *(const float4*)(Bsrc + (size_t)r0 * Bst + k1 + c40);
                pb1 = *(const float4*)(Bsrc + (size_t)r1 * Bst + k1 + c40);
            }
        }

        // fragments
        uint32_t ah[4][4], bh[8][2];
        #pragma unroll
        for (int mf = 0; mf < 4; ++mf) {
            int R0 = wm * 64 + mf * 16 + g, R1 = R0 + 8;
            ah[mf][0] = AH[R0 * 8 + (t ^ (R0 & 7))];
            ah[mf][1] = AH[R1 * 8 + (t ^ (R1 & 7))];
            ah[mf][2] = AH[R0 * 8 + ((t + 4) ^ (R0 & 7))];
            ah[mf][3] = AH[R1 * 8 + ((t + 4) ^ (R1 & 7))];
        }
        #pragma unroll
        for (int nf = 0; nf < 8; ++nf) {
            int Rn = wn * 64 + nf * 8 + g;
            bh[nf][0] = BH[Rn * 8 + (t ^ (Rn & 7))];
            bh[nf][1] = BH[Rn * 8 + ((t + 4) ^ (Rn & 7))];
        }
        // term 1: hi x hi
        #pragma unroll
        for (int mf = 0; mf < 4; ++mf)
            #pragma unroll
            for (int nf = 0; nf < 8; ++nf)
                MMA_F16(acc[mf][nf], ah[mf], bh[nf]);
        // term 2: hi_A x lo_B
        {
            uint32_t bl[8][2];
            #pragma unroll
            for (int nf = 0; nf < 8; ++nf) {
                int Rn = wn * 64 + nf * 8 + g;
                bl[nf][0] = BL[Rn * 8 + (t ^ (Rn & 7))];
                bl[nf][1] = BL[Rn * 8 + ((t + 4) ^ (Rn & 7))];
            }
            #pragma unroll
            for (int mf = 0; mf < 4; ++mf)
                #pragma unroll
                for (int nf = 0; nf < 8; ++nf)
                    MMA_F16(acc[mf][nf], ah[mf], bl[nf]);
        }
        // term 3: lo_A x hi_B
        {
            uint32_t al[4][4];
            #pragma unroll
            for (int mf = 0; mf < 4; ++mf) {
                int R0 = wm * 64 + mf * 16 + g, R1 = R0 + 8;
                al[mf][0] = AL[R0 * 8 + (t ^ (R0 & 7))];
                al[mf][1] = AL[R1 * 8 + (t ^ (R1 & 7))];
                al[mf][2] = AL[R0 * 8 + ((t + 4) ^ (R0 & 7))];
                al[mf][3] = AL[R1 * 8 + ((t + 4) ^ (R1 & 7))];
            }
            #pragma unroll
            for (int mf = 0; mf < 4; ++mf)
                #pragma unroll
                for (int nf = 0; nf < 8; ++nf)
                    MMA_F16(acc[mf][nf], al[mf], bh[nf]);
        }
        __syncthreads();

        if (pf) {
            const int nxt = (c + 1) & 1;
            #pragma unroll
            for (int i = 0; i < 4; ++i) {
                int id = tid + (i << 8), r = id >> 2, c4 = (id & 3) << 2;
                putA4(nxt, r, c4, pa[i]);
            }
            if (MODE == 1) {
                int kp = tid >> 5, nb = (tid & 31) << 2;
                putB_T(nxt, kp, nb, pb0, pb1);
            } else {
                int r0 = tid >> 2,         c40 = (tid & 3) << 2;
                int r1 = (tid + 256) >> 2;
                putB4(nxt, r0, c40, pb0);
                putB4(nxt, r1, c40, pb1);
            }
            __syncthreads();
        }
    }
    __syncthreads();

    // ---- epilogue ----
    if (MODE == 0) {
        const int head = blockIdx.x;
        #pragma unroll
        for (int mf = 0; mf < 4; ++mf)
            #pragma unroll
            for (int hh = 0; hh < 2; ++hh) {
                int m = m0 + wm * 64 + mf * 16 + g + 8 * hh;
                int bidx = m >> 10, tok = m & 1023;
                float* dst = g_X + (((size_t)bidx * Hh + head) * Nn + tok) * Dd;
                #pragma unroll
                for (int nf = 0; nf < 8; ++nf) {
                    int col = wn * 64 + nf * 8 + 2 * t;
                    float b0 = P2[n0 + col], b1 = P2[n0 + col + 1];
                    *(float2*)(dst + col) =
                        make_float2(acc[mf][nf][2*hh+0] + b0,
                                    acc[mf][nf][2*hh+1] + b1);
                }
            }
    } else if (MODE == 1) {
        #pragma unroll
        for (int mf = 0; mf < 4; ++mf)
            #pragma unroll
            for (int hh = 0; hh < 2; ++hh) {
                int m = m0 + wm * 64 + mf * 16 + g + 8 * hh;
                float* dst = g_XM + (size_t)m * Dd;
                #pragma unroll
                for (int nf = 0; nf < 8; ++nf) {
                    int col = wn * 64 + nf * 8 + 2 * t;
                    *(float2*)(dst + col) =
                        make_float2(acc[mf][nf][2*hh+0], acc[mf][nf][2*hh+1]);
                }
            }
    } else {  // MODE 2
        float rsum[4][2];
        #pragma unroll
        for (int mf = 0; mf < 4; ++mf) { rsum[mf][0] = 0.f; rsum[mf][1] = 0.f; }
        #pragma unroll
        for (int mf = 0; mf < 4; ++mf)
            #pragma unroll
            for (int hh = 0; hh < 2; ++hh) {
                int rm = wm * 64 + mf * 16 + g + 8 * hh;
                float* dst = g_P + (z * Nn + m0 + rm) * (size_t)Nn + n0;
                #pragma unroll
                for (int nf = 0; nf < 8; ++nf) {
                    int col = wn * 64 + nf * 8 + 2 * t;
                    float e0 = __expf(acc[mf][nf][2*hh+0]);
                    float e1 = __expf(acc[mf][nf][2*hh+1]);
                    rsum[mf][hh] += e0 + e1;
                    *(float2*)(dst + col) = make_float2(e0, e1);
                }
            }
        float* ssum = (float*)smw;   // alias A buf (compute done)
        #pragma unroll
        for (int mf = 0; mf < 4; ++mf)
            #pragma unroll
            for (int hh = 0; hh < 2; ++hh) {
                float s = rsum[mf][hh];
                s += __shfl_xor_sync(0xffffffffu, s, 1);
                s += __shfl_xor_sync(0xffffffffu, s, 2);
                if (t == 0)
                    ssum[(wm * 64 + mf * 16 + g + 8 * hh) * 2 + wn] = s;
            }
        __syncthreads();
        {
            float l = ssum[tid * 2] + ssum[tid * 2 + 1];
            g_L[(z * Nn + m0 + tid) * 8 + blockIdx.x] = l;
        }
    }
}

// ===========================================================================
// MODE 3 (PV) — single-pass TF32 (unchanged math from round 5).
// smem floats: A[2][5120]@0, B[2][2560]@10240 -> 61440 B.
// ===========================================================================
#define APITCH 20
#define ABUF   5120
#define BHIo   10240
#define BBUF   2560
#define SMEM_PV 61440

__global__ void __launch_bounds__(256, 1) k_pv()
{
    extern __shared__ float smf[];
    uint32_t* smU = (uint32_t*)smf;

    const int tid  = threadIdx.x;
    const int wid  = tid >> 5, lane = tid & 31;
    const int wm   = wid >> 1, wn = wid & 1;
    const int g    = lane >> 2, t = lane & 3;

    const size_t z = blockIdx.y;
    const int m0   = blockIdx.x * 256;
    const float* Asrc = g_P  + (z * Nn + m0) * (size_t)Nn;  int Ast = Nn;
    const float* Bsrc = g_XT + z * (size_t)(Dd * Nn);       int Bst = Nn;

    constexpr int NC = 64;

    float acc[4][8][4];
    #pragma unroll
    for (int a = 0; a < 4; ++a)
        #pragma unroll
        for (int b = 0; b < 8; ++b)
            #pragma unroll
            for (int cix = 0; cix < 4; ++cix) acc[a][b][cix] = 0.f;

    {
        #pragma unroll
        for (int i = 0; i < 4; ++i) {
            int id = tid + (i << 8), r = id >> 2, c4 = (id & 3) << 2;
            float4 f = *(const float4*)(Asrc + (size_t)r * Ast + c4);
            *(uint4*)&smU[r * APITCH + c4] =
                make_uint4(f2tf32(f.x), f2tf32(f.y), f2tf32(f.z), f2tf32(f.w));
        }
        #pragma unroll
        for (int i = 0; i < 2; ++i) {
            int id = tid + (i << 8), r = id >> 2, c4 = (id & 3) << 2;
            float4 f = *(const float4*)(Bsrc + (size_t)r * Bst + c4);
            *(uint4*)&smU[BHIo + r * APITCH + c4] =
                make_uint4(f2tf32(f.x), f2tf32(f.y), f2tf32(f.z), f2tf32(f.w));
        }
    }
    __syncthreads();

    for (int c = 0; c < NC; ++c) {
        const int cur = c & 1;
        const uint32_t* As = smU + cur * ABUF;
        const uint32_t* Bs = smU + BHIo + cur * BBUF;

        float4 pa[4]; float4 pb0, pb1;
        const bool pf = (c + 1 < NC);
        const int k1 = (c + 1) << 4;
        if (pf) {
            #pragma unroll
            for (int i = 0; i < 4; ++i) {
                int id = tid + (i << 8), r = id >> 2, c4 = (id & 3) << 2;
                pa[i] = *(const float4*)(Asrc + (size_t)r * Ast + k1 + c4);
            }
            int r0 = tid >> 2,         c40 = (tid & 3) << 2;
            int r1 = (tid + 256) >> 2;
            pb0 = *(const float4*)(Bsrc + (size_t)r0 * Bst + k1 + c40);
            pb1 = *(const float4*)(Bsrc + (size_t)r1 * Bst + k1 + c40);
        }

        #pragma unroll
        for (int ks = 0; ks < 2; ++ks) {
            uint32_t af[4][4], bf[8][2];
            #pragma unroll
            for (int mf = 0; mf < 4; ++mf) {
                int base = (wm * 64 + mf * 16 + g) * APITCH + ks * 8 + t;
                af[mf][0] = As[base];
                af[mf][1] = As[base + 8 * APITCH];
                af[mf][2] = As[base + 4];
                af[mf][3] = As[base + 8 * APITCH + 4];
            }
            #pragma unroll
            for (int nf = 0; nf < 8; ++nf) {
                int base = (wn * 64 + nf * 8 + g) * APITCH + ks * 8 + t;
                bf[nf][0] = Bs[base];
                bf[nf][1] = Bs[base + 4];
            }
            #pragma unroll
            for (int mf = 0; mf < 4; ++mf)
                #pragma unroll
                for (int nf = 0; nf < 8; ++nf)
                    MMA_TF32(acc[mf][nf], af[mf], bf[nf]);
        }
        __syncthreads();

        if (pf) {
            const int nxt = (c + 1) & 1;
            #pragma unroll
            for (int i = 0; i < 4; ++i) {
                int id = tid + (i << 8), r = id >> 2, c4 = (id & 3) << 2;
                *(uint4*)&smU[nxt * ABUF + r * APITCH + c4] =
                    make_uint4(f2tf32(pa[i].x), f2tf32(pa[i].y),
                               f2tf32(pa[i].z), f2tf32(pa[i].w));
            }
            int r0 = tid >> 2,         c40 = (tid & 3) << 2;
            int r1 = (tid + 256) >> 2;
            *(uint4*)&smU[BHIo + nxt * BBUF + r0 * APITCH + c40] =
                make_uint4(f2tf32(pb0.x), f2tf32(pb0.y), f2tf32(pb0.z), f2tf32(pb0.w));
            *(uint4*)&smU[BHIo + nxt * BBUF + r1 * APITCH + c40] =
                make_uint4(f2tf32(pb1.x), f2tf32(pb1.y), f2tf32(pb1.z), f2tf32(pb1.w));
            __syncthreads();
        }
    }
    __syncthreads();

    #pragma unroll
    for (int mf = 0; mf < 4; ++mf)
        #pragma unroll
        for (int hh = 0; hh < 2; ++hh) {
            size_t row = z * Nn + m0 + wm * 64 + mf * 16 + g + 8 * hh;
            const float* lp = g_L + row * 8;
            float l = ((lp[0] + lp[1]) + (lp[2] + lp[3]))
                    + ((lp[4] + lp[5]) + (lp[6] + lp[7]));
            float inv = 1.f / l;
            float* dst = g_O + row * (size_t)Dd;
            #pragma unroll
            for (int nf = 0; nf < 8; ++nf) {
                int col = wn * 64 + nf * 8 + 2 * t;
                *(float2*)(dst + col) =
                    make_float2(acc[mf][nf][2*hh+0] * inv,
                                acc[mf][nf][2*hh+1] * inv);
            }
        }
}

// ---------------------------------------------------------------------------
// Transpose: g_XT[z][d][n] = g_X[z][n][d]
// ---------------------------------------------------------------------------
__global__ void __launch_bounds__(256) k_transpose()
{
    __shared__ float tsm[32][33];
    const int z  = blockIdx.z;
    const int d0 = blockIdx.y << 5;
    const int nb = blockIdx.x << 5;
    const int lx = threadIdx.x, ly = threadIdx.y;
    const float* src = g_X + (size_t)z * Nn * Dd;
    #pragma unroll
    for (int i = 0; i < 32; i += 8)
        tsm[ly + i][lx] = src[(size_t)(nb + ly + i) * Dd + d0 + lx];
    __syncthreads();
    float* dst = g_XT + (size_t)z * Dd * Nn;
    #pragma unroll
    for (int i = 0; i < 32; i += 8)
        dst[(size_t)(d0 + ly + i) * Nn + nb + lx] = tsm[lx][ly + i];
}

// ---------------------------------------------------------------------------
// LayerNorm + exact GELU over c (gather heads)
// ---------------------------------------------------------------------------
__global__ void __launch_bounds__(256) k_ln_gelu(const float* __restrict__ gamma,
                                                 const float* __restrict__ beta,
                                                 float* __restrict__ out)
{
    const int row = blockIdx.x;
    const int bbi = row >> 10, nn = row & 1023;
    const int tid = threadIdx.x;
    const int c0 = tid * 4, head = c0 >> 7, dd = c0 & 127;

    const float* src = g_O + (((size_t)bbi * Hh + head) * Nn + nn) * Dd + dd;
    float4 v = *(const float4*)src;

    float s = v.x + v.y + v.z + v.w;
    float q = v.x*v.x + v.y*v.y + v.z*v.z + v.w*v.w;
    #pragma unroll
    for (int off = 16; off >= 1; off >>= 1) {
        s += __shfl_xor_sync(0xffffffffu, s, off);
        q += __shfl_xor_sync(0xffffffffu, q, off);
    }
    __shared__ float ss[8], sq[8];
    if ((tid & 31) == 0) { ss[tid >> 5] = s; sq[tid >> 5] = q; }
    __syncthreads();
    float st = 0.f, qt = 0.f;
    #pragma unroll
    for (int k = 0; k < 8; ++k) { st += ss[k]; qt += sq[k]; }

    const float mean = st * (1.f / (float)Cc);
    const float var  = qt * (1.f / (float)Cc) - mean * mean;
    const float rstd = rsqrtf(var + 1e-5f);

    float4 gm = *(const float4*)(gamma + c0);
    float4 be = *(const float4*)(beta + c0);
    float y0 = (v.x - mean) * rstd * gm.x + be.x;
    float y1 = (v.y - mean) * rstd * gm.y + be.y;
    float y2 = (v.z - mean) * rstd * gm.z + be.z;
    float y3 = (v.w - mean) * rstd * gm.w + be.w;

    const float k2 = 0.70710678118654752440f;
    float4 rr;
    rr.x = 0.5f * y0 * (1.f + erff(y0 * k2));
    rr.y = 0.5f * y1 * (1.f + erff(y1 * k2));
    rr.z = 0.5f * y2 * (1.f + erff(y2 * k2));
    rr.w = 0.5f * y3 * (1.f + erff(y3 * k2));
    *(float4*)(out + (size_t)row * Cc + c0) = rr;
}

// ---------------------------------------------------------------------------
extern "C" void kernel_launch(void* const* d_in, const int* in_sizes, int n_in,
                              void* d_out, int out_size)
{
    const float* h     = (const float*)d_in[0];
    const float* W_w   = (const float*)d_in[1];
    const float* W_b   = (const float*)d_in[2];
    const float* Mmat  = (const float*)d_in[3];
    const float* gamma = (const float*)d_in[4];
    const float* beta  = (const float*)d_in[5];
    float* out = (float*)d_out;

    cudaFuncSetAttribute(k_f16<0>, cudaFuncAttributeMaxDynamicSharedMemorySize, SMEM_F16);
    cudaFuncSetAttribute(k_f16<1>, cudaFuncAttributeMaxDynamicSharedMemorySize, SMEM_F16);
    cudaFuncSetAttribute(k_f16<2>, cudaFuncAttributeMaxDynamicSharedMemorySize, SMEM_F16);
    cudaFuncSetAttribute(k_pv,     cudaFuncAttributeMaxDynamicSharedMemorySize, SMEM_PV);

    // 1) X = h @ W^T + b               -> g_X [z][n][d]     (fp16 3-term)
    k_f16<0><<<dim3(Hh, MROWS / 256), 256, SMEM_F16>>>(h, W_w, W_b);
    // 2) X^T                           -> g_XT [z][d][n]
    k_transpose<<<dim3(Nn / 32, Dd / 32, BHn), dim3(32, 8)>>>();
    // 3) XM = X @ M                    -> g_XM              (fp16 3-term)
    k_f16<1><<<dim3((BHn * Nn) / 256), 256, SMEM_F16>>>(nullptr, Mmat, nullptr);
    // 4) P = exp(XM @ X^T), lpart      -> g_P, g_L          (fp16 3-term)
    k_f16<2><<<dim3(Nn / 128, Nn / 256, BHn), 256, SMEM_F16>>>(nullptr, nullptr, nullptr);
    // 5) O = (P @ V) / l               -> g_O               (1x tf32)
    k_pv<<<dim3(Nn / 256, BHn), 256, SMEM_PV>>>();
    // 6) LayerNorm + GELU              -> out
    k_ln_gelu<<<MROWS, 256>>>(gamma, beta, out);
}

// round 9
// speedup vs baseline: 3.5062x; 1.1804x over previous
#include <cuda_runtime.h>
#include <cuda_fp16.h>
#include <stdint.h>
#include <math.h>

// Fixed shapes for GraphAttentionLayer_18021682774974
#define Bb  32
#define Nn  1024
#define Cc  1024
#define Hh  8
#define Dd  128
#define BHn 256
#define MROWS (Bb * Nn)              // 32768
#define XW  (BHn * Nn * Dd)          // 33.5M

// log-domain shift so P = exp(S - PSHIFT) fits fp16 (S_max ~ 16 << 23.1).
// Cancels exactly in O = (P@V) / rowsum(P).
#define PSHIFT 12.0f

// Pre-split half operands + scratch (device globals; no cudaMalloc allowed)
__device__ __half g_hh [MROWS * Cc], g_hl [MROWS * Cc];   // h split
__device__ __half g_Wh [Cc * Cc],    g_Wl [Cc * Cc];      // W split
__device__ __half g_Mth[Dd * Dd],    g_Mtl[Dd * Dd];      // M^T split
__device__ __half g_Xh [XW], g_Xl [XW];                   // X  [z][n][d]
__device__ __half g_XMh[XW], g_XMl[XW];                   // XM [z][n][d]
__device__ __half g_VTh[XW], g_VTl[XW];                   // X^T [z][d][n]
__device__ __half g_Ph [(size_t)BHn * Nn * Nn];           // P fp16 (512MB)
__device__ float  g_L  [BHn * Nn * 8];                    // row-sum partials
__device__ float  g_O  [XW];                              // attention out

// ---------------------------------------------------------------------------
__device__ __forceinline__ uint32_t smem_u32(const void* p) {
    uint32_t a;
    asm("{ .reg .u64 t; cvta.to.shared.u64 t, %1; cvt.u32.u64 %0, t; }"
        : "=r"(a) : "l"(p));
    return a;
}
__device__ __forceinline__ void cp16(uint32_t sa, const void* gp) {
    asm volatile("cp.async.cg.shared.global [%0], [%1], 16;" :: "r"(sa), "l"(gp));
}
#define CP_COMMIT() asm volatile("cp.async.commit_group;" ::: "memory")
#define CP_WAIT1()  asm volatile("cp.async.wait_group 1;" ::: "memory")

#define MMA_F16(d, a, b)                                                      \
    asm volatile("mma.sync.aligned.m16n8k16.row.col.f32.f16.f16.f32 "         \
                 "{%0,%1,%2,%3}, {%4,%5,%6,%7}, {%8,%9}, {%0,%1,%2,%3};"      \
                 : "+f"((d)[0]), "+f"((d)[1]), "+f"((d)[2]), "+f"((d)[3])     \
                 : "r"((a)[0]), "r"((a)[1]), "r"((a)[2]), "r"((a)[3]),        \
                   "r"((b)[0]), "r"((b)[1]))

// ---------------------------------------------------------------------------
// Elementwise fp32 -> fp16 hi/lo split (vectorized float4)
// ---------------------------------------------------------------------------
__global__ void __launch_bounds__(256) k_split(const float* __restrict__ src,
                                               __half* __restrict__ hi,
                                               __half* __restrict__ lo, int n4)
{
    int i = blockIdx.x * 256 + threadIdx.x;
    if (i >= n4) return;
    float4 v = ((const float4*)src)[i];
    __half h0 = __float2half_rn(v.x), h1 = __float2half_rn(v.y);
    __half h2 = __float2half_rn(v.z), h3 = __float2half_rn(v.w);
    ((__half2*)hi)[2*i]   = __halves2half2(h0, h1);
    ((__half2*)hi)[2*i+1] = __halves2half2(h2, h3);
    ((__half2*)lo)[2*i]   = __floats2half2_rn(v.x - __half2float(h0),
                                              v.y - __half2float(h1));
    ((__half2*)lo)[2*i+1] = __floats2half2_rn(v.z - __half2float(h2),
                                              v.w - __half2float(h3));
}

// M^T split (tiny, one block)
__global__ void __launch_bounds__(256) k_splitMt(const float* __restrict__ M)
{
    for (int i = threadIdx.x; i < Dd * Dd; i += 256) {
        int e = i >> 7, k = i & 127;
        float v = M[k * Dd + e];
        __half h = __float2half_rn(v);
        g_Mth[i] = h;
        g_Mtl[i] = __float2half_rn(v - __half2float(h));
    }
}

// ===========================================================================
// Unified f16 GEMM, cp.async 3-stage pipeline.  D[256x128] = A @ B^T.
// Operands pre-split in global as half. K-chunk = 32 halfs.
// smem word layout per stage: AH[4096] (+AL[4096] if 3-term), BH[2048], BL[2048]
// 16B chunk (row r, ch of 4) stored at chunk index (ch ^ ((r>>1)&3)).
// MODE 0: X  = h @ W^T + bias  (3-term) K=1024  grid (8 heads, 128 mt)
// MODE 1: XM = X @ M           (3-term) K=128   grid (1024)
// MODE 2: P  = exp(XM@X^T - PSHIFT)     K=128   grid (8 nt, 4 mt, 256 z)
// MODE 3: O  = (P @ V) / l     (2-term) K=1024  grid (4 mt, 256 z)
// ===========================================================================
template<int MODE>
__global__ void __launch_bounds__(256, 1) k_gemm(const float* __restrict__ bias)
{
    extern __shared__ uint32_t smw[];
    constexpr bool ALO = (MODE != 3);
    constexpr int  STG = ALO ? 12288 : 8192;        // words per stage
    constexpr int  NC  = (MODE == 0 || MODE == 3) ? 32 : 4;

    const int tid = threadIdx.x;
    const int wid = tid >> 5, lane = tid & 31;
    const int wm  = wid >> 1, wn = wid & 1;
    const int g   = lane >> 2, t = lane & 3;
    const uint32_t xr = (uint32_t)((g & 6) << 1);
    const uint32_t sbase = smem_u32(smw);

    int m0 = 0, n0 = 0; size_t z = 0;
    const __half *Ah = nullptr, *Al = nullptr, *Bh = nullptr, *Bl = nullptr;
    int Ast = 0, Bst = 0;
    if (MODE == 0) {
        m0 = blockIdx.y * 256; n0 = blockIdx.x * 128;
        Ah = g_hh + (size_t)m0 * Cc;  Al = g_hl + (size_t)m0 * Cc;  Ast = Cc;
        Bh = g_Wh + (size_t)n0 * Cc;  Bl = g_Wl + (size_t)n0 * Cc;  Bst = Cc;
    } else if (MODE == 1) {
        m0 = blockIdx.x * 256;
        Ah = g_Xh + (size_t)m0 * Dd;  Al = g_Xl + (size_t)m0 * Dd;  Ast = Dd;
        Bh = g_Mth;                   Bl = g_Mtl;                   Bst = Dd;
    } else if (MODE == 2) {
        z = blockIdx.z; m0 = blockIdx.y * 256; n0 = blockIdx.x * 128;
        Ah = g_XMh + (z * Nn + m0) * (size_t)Dd;
        Al = g_XMl + (z * Nn + m0) * (size_t)Dd;  Ast = Dd;
        Bh = g_Xh  + (z * Nn + n0) * (size_t)Dd;
        Bl = g_Xl  + (z * Nn + n0) * (size_t)Dd;  Bst = Dd;
    } else {
        z = blockIdx.y; m0 = blockIdx.x * 256;
        Ah = g_Ph  + (z * Nn + m0) * (size_t)Nn;  Ast = Nn;
        Bh = g_VTh + z * (size_t)(Dd * Nn);
        Bl = g_VTl + z * (size_t)(Dd * Nn);       Bst = Nn;
    }

    float acc[4][8][4];
    #pragma unroll
    for (int a = 0; a < 4; ++a)
        #pragma unroll
        for (int b = 0; b < 8; ++b)
            #pragma unroll
            for (int c = 0; c < 4; ++c) acc[a][b][c] = 0.f;

    auto load_stage = [&](int st, int k0) {
        const uint32_t sb = sbase + (uint32_t)st * STG * 4;
        #pragma unroll
        for (int i = 0; i < 4; ++i) {                       // A: 256r x 4 chunks
            int idx = tid + (i << 8);
            int r = idx >> 2, ch = idx & 3;
            uint32_t d = sb + (uint32_t)(r * 16 + ((ch ^ ((r >> 1) & 3)) << 2)) * 4;
            const size_t go = (size_t)r * Ast + k0 + ch * 8;
            cp16(d, Ah + go);
            if (ALO) cp16(d + 4096 * 4, Al + go);
        }
        const uint32_t bo = (ALO ? 8192u : 4096u) * 4;
        #pragma unroll
        for (int i = 0; i < 2; ++i) {                       // B: 128r x 4 chunks
            int idx = tid + (i << 8);
            int r = idx >> 2, ch = idx & 3;
            uint32_t d = sb + bo + (uint32_t)(r * 16 + ((ch ^ ((r >> 1) & 3)) << 2)) * 4;
            const size_t go = (size_t)r * Bst + k0 + ch * 8;
            cp16(d, Bh + go);
            cp16(d + 2048 * 4, Bl + go);
        }
    };

    // prologue
    load_stage(0, 0);  CP_COMMIT();
    load_stage(1, 32); CP_COMMIT();

    for (int c = 0; c < NC; ++c) {
        CP_WAIT1();
        __syncthreads();
        if (c + 2 < NC) load_stage((c + 2) % 3, (c + 2) * 32);
        CP_COMMIT();

        const int st = c % 3;
        const uint32_t* AH = smw + st * STG;
        const uint32_t* AL = AH + 4096;
        const uint32_t* BH = smw + st * STG + (ALO ? 8192 : 4096);
        const uint32_t* BL = BH + 2048;

        #pragma unroll
        for (int ks = 0; ks < 2; ++ks) {
            const uint32_t w0 = (uint32_t)(ks * 8 + t) ^ xr;
            const uint32_t w1 = (uint32_t)(ks * 8 + t + 4) ^ xr;
            uint32_t ah[4][4], bb[8][2];
            #pragma unroll
            for (int mf = 0; mf < 4; ++mf) {
                int R0 = (wm * 64 + mf * 16 + g) * 16, R1 = R0 + 128;
                ah[mf][0] = AH[R0 + w0];
                ah[mf][1] = AH[R1 + w0];
                ah[mf][2] = AH[R0 + w1];
                ah[mf][3] = AH[R1 + w1];
            }
            #pragma unroll
            for (int nf = 0; nf < 8; ++nf) {
                int Rn = (wn * 64 + nf * 8 + g) * 16;
                bb[nf][0] = BH[Rn + w0];
                bb[nf][1] = BH[Rn + w1];
            }
            // term 1: A_hi x B_hi
            #pragma unroll
            for (int mf = 0; mf < 4; ++mf)
                #pragma unroll
                for (int nf = 0; nf < 8; ++nf)
                    MMA_F16(acc[mf][nf], ah[mf], bb[nf]);
            // term 3 (3-term only): A_lo x B_hi   (B_hi still live)
            if (ALO) {
                uint32_t al[4][4];
                #pragma unroll
                for (int mf = 0; mf < 4; ++mf) {
                    int R0 = (wm * 64 + mf * 16 + g) * 16, R1 = R0 + 128;
                    al[mf][0] = AL[R0 + w0];
                    al[mf][1] = AL[R1 + w0];
                    al[mf][2] = AL[R0 + w1];
                    al[mf][3] = AL[R1 + w1];
                }
                #pragma unroll
                for (int mf = 0; mf < 4; ++mf)
                    #pragma unroll
                    for (int nf = 0; nf < 8; ++nf)
                        MMA_F16(acc[mf][nf], al[mf], bb[nf]);
            }
            // term 2: A_hi x B_lo
            #pragma unroll
            for (int nf = 0; nf < 8; ++nf) {
                int Rn = (wn * 64 + nf * 8 + g) * 16;
                bb[nf][0] = BL[Rn + w0];
                bb[nf][1] = BL[Rn + w1];
            }
            #pragma unroll
            for (int mf = 0; mf < 4; ++mf)
                #pragma unroll
                for (int nf = 0; nf < 8; ++nf)
                    MMA_F16(acc[mf][nf], ah[mf], bb[nf]);
        }
    }
    __syncthreads();

    // ---- epilogue ----
    if (MODE == 0) {
        const int head = blockIdx.x;
        #pragma unroll
        for (int mf = 0; mf < 4; ++mf)
            #pragma unroll
            for (int hh = 0; hh < 2; ++hh) {
                int m = m0 + wm * 64 + mf * 16 + g + 8 * hh;
                int bidx = m >> 10, tok = m & 1023;
                size_t ro = (((size_t)bidx * Hh + head) * Nn + tok) * Dd;
                #pragma unroll
                for (int nf = 0; nf < 8; ++nf) {
                    int col = wn * 64 + nf * 8 + 2 * t;
                    float v0 = acc[mf][nf][2*hh+0] + bias[n0 + col];
                    float v1 = acc[mf][nf][2*hh+1] + bias[n0 + col + 1];
                    __half h0 = __float2half_rn(v0), h1 = __float2half_rn(v1);
                    *(__half2*)(g_Xh + ro + col) = __halves2half2(h0, h1);
                    *(__half2*)(g_Xl + ro + col) =
                        __floats2half2_rn(v0 - __half2float(h0),
                                          v1 - __half2float(h1));
                }
            }
    } else if (MODE == 1) {
        #pragma unroll
        for (int mf = 0; mf < 4; ++mf)
            #pragma unroll
            for (int hh = 0; hh < 2; ++hh) {
                size_t ro = (size_t)(m0 + wm * 64 + mf * 16 + g + 8 * hh) * Dd;
                #pragma unroll
                for (int nf = 0; nf < 8; ++nf) {
                    int col = wn * 64 + nf * 8 + 2 * t;
                    float v0 = acc[mf][nf][2*hh+0], v1 = acc[mf][nf][2*hh+1];
                    __half h0 = __float2half_rn(v0), h1 = __float2half_rn(v1);
                    *(__half2*)(g_XMh + ro + col) = __halves2half2(h0, h1);
                    *(__half2*)(g_XMl + ro + col) =
                        __floats2half2_rn(v0 - __half2float(h0),
                                          v1 - __half2float(h1));
                }
            }
    } else if (MODE == 2) {
        float rsum[4][2];
        #pragma unroll
        for (int mf = 0; mf < 4; ++mf) { rsum[mf][0] = 0.f; rsum[mf][1] = 0.f; }
        #pragma unroll
        for (int mf = 0; mf < 4; ++mf)
            #pragma unroll
            for (int hh = 0; hh < 2; ++hh) {
                int rm = wm * 64 + mf * 16 + g + 8 * hh;
                __half* dst = g_Ph + (z * Nn + m0 + rm) * (size_t)Nn + n0;
                #pragma unroll
                for (int nf = 0; nf < 8; ++nf) {
                    int col = wn * 64 + nf * 8 + 2 * t;
                    __half p0 = __float2half_rn(__expf(acc[mf][nf][2*hh+0] - PSHIFT));
                    __half p1 = __float2half_rn(__expf(acc[mf][nf][2*hh+1] - PSHIFT));
                    rsum[mf][hh] += __half2float(p0) + __half2float(p1);
                    *(__half2*)(dst + col) = __halves2half2(p0, p1);
                }
            }
        float* ssum = (float*)smw;   // alias stage smem (compute done)
        #pragma unroll
        for (int mf = 0; mf < 4; ++mf)
            #pragma unroll
            for (int hh = 0; hh < 2; ++hh) {
                float s = rsum[mf][hh];
                s += __shfl_xor_sync(0xffffffffu, s, 1);
                s += __shfl_xor_sync(0xffffffffu, s, 2);
                if (t == 0)
                    ssum[(wm * 64 + mf * 16 + g + 8 * hh) * 2 + wn] = s;
            }
        __syncthreads();
        {
            float l = ssum[tid * 2] + ssum[tid * 2 + 1];
            g_L[(z * Nn + m0 + tid) * 8 + blockIdx.x] = l;
        }
    } else {  // MODE 3 (PV)
        #pragma unroll
        for (int mf = 0; mf < 4; ++mf)
            #pragma unroll
            for (int hh = 0; hh < 2; ++hh) {
                size_t row = z * Nn + m0 + wm * 64 + mf * 16 + g + 8 * hh;
                const float* lp = g_L + row * 8;
                float l = ((lp[0] + lp[1]) + (lp[2] + lp[3]))
                        + ((lp[4] + lp[5]) + (lp[6] + lp[7]));
                float inv = 1.f / l;
                float* dst = g_O + row * (size_t)Dd;
                #pragma unroll
                for (int nf = 0; nf < 8; ++nf) {
                    int col = wn * 64 + nf * 8 + 2 * t;
                    *(float2*)(dst + col) =
                        make_float2(acc[mf][nf][2*hh+0] * inv,
                                    acc[mf][nf][2*hh+1] * inv);
                }
            }
    }
}

// ---------------------------------------------------------------------------
// Transpose X_hi/X_lo -> VT_hi/VT_lo  ([z][n][d] -> [z][d][n])
// ---------------------------------------------------------------------------
__global__ void __launch_bounds__(256) k_transpose()
{
    __shared__ __half th[32][33], tl[32][33];
    const int z  = blockIdx.z;
    const int d0 = blockIdx.y << 5;
    const int nb = blockIdx.x << 5;
    const int lx = threadIdx.x, ly = threadIdx.y;
    const __half* sh = g_Xh + (size_t)z * Nn * Dd;
    const __half* sl = g_Xl + (size_t)z * Nn * Dd;
    #pragma unroll
    for (int i = 0; i < 32; i += 8) {
        th[ly + i][lx] = sh[(size_t)(nb + ly + i) * Dd + d0 + lx];
        tl[ly + i][lx] = sl[(size_t)(nb + ly + i) * Dd + d0 + lx];
    }
    __syncthreads();
    __half* dh = g_VTh + (size_t)z * Dd * Nn;
    __half* dl = g_VTl + (size_t)z * Dd * Nn;
    #pragma unroll
    for (int i = 0; i < 32; i += 8) {
        dh[(size_t)(d0 + ly + i) * Nn + nb + lx] = th[lx][ly + i];
        dl[(size_t)(d0 + ly + i) * Nn + nb + lx] = tl[lx][ly + i];
    }
}

// ---------------------------------------------------------------------------
// LayerNorm + exact GELU over c (gather heads)
// ---------------------------------------------------------------------------
__global__ void __launch_bounds__(256) k_ln_gelu(const float* __restrict__ gamma,
                                                 const float* __restrict__ beta,
                                                 float* __restrict__ out)
{
    const int row = blockIdx.x;
    const int bbi = row >> 10, nn = row & 1023;
    const int tid = threadIdx.x;
    const int c0 = tid * 4, head = c0 >> 7, dd = c0 & 127;

    const float* src = g_O + (((size_t)bbi * Hh + head) * Nn + nn) * Dd + dd;
    float4 v = *(const float4*)src;

    float s = v.x + v.y + v.z + v.w;
    float q = v.x*v.x + v.y*v.y + v.z*v.z + v.w*v.w;
    #pragma unroll
    for (int off = 16; off >= 1; off >>= 1) {
        s += __shfl_xor_sync(0xffffffffu, s, off);
        q += __shfl_xor_sync(0xffffffffu, q, off);
    }
    __shared__ float ss[8], sq[8];
    if ((tid & 31) == 0) { ss[tid >> 5] = s; sq[tid >> 5] = q; }
    __syncthreads();
    float st = 0.f, qt = 0.f;
    #pragma unroll
    for (int k = 0; k < 8; ++k) { st += ss[k]; qt += sq[k]; }

    const float mean = st * (1.f / (float)Cc);
    const float var  = qt * (1.f / (float)Cc) - mean * mean;
    const float rstd = rsqrtf(var + 1e-5f);

    float4 gm = *(const float4*)(gamma + c0);
    float4 be = *(const float4*)(beta + c0);
    float y0 = (v.x - mean) * rstd * gm.x + be.x;
    float y1 = (v.y - mean) * rstd * gm.y + be.y;
    float y2 = (v.z - mean) * rstd * gm.z + be.z;
    float y3 = (v.w - mean) * rstd * gm.w + be.w;

    const float k2 = 0.70710678118654752440f;
    float4 rr;
    rr.x = 0.5f * y0 * (1.f + erff(y0 * k2));
    rr.y = 0.5f * y1 * (1.f + erff(y1 * k2));
    rr.z = 0.5f * y2 * (1.f + erff(y2 * k2));
    rr.w = 0.5f * y3 * (1.f + erff(y3 * k2));
    *(float4*)(out + (size_t)row * Cc + c0) = rr;
}

// ---------------------------------------------------------------------------
#define SMEM_3T (3 * 12288 * 4)   // 147456 B
#define SMEM_2T (3 * 8192 * 4)    //  98304 B

extern "C" void kernel_launch(void* const* d_in, const int* in_sizes, int n_in,
                              void* d_out, int out_size)
{
    const float* h     = (const float*)d_in[0];
    const float* W_w   = (const float*)d_in[1];
    const float* W_b   = (const float*)d_in[2];
    const float* Mmat  = (const float*)d_in[3];
    const float* gamma = (const float*)d_in[4];
    const float* beta  = (const float*)d_in[5];
    float* out = (float*)d_out;

    cudaFuncSetAttribute(k_gemm<0>, cudaFuncAttributeMaxDynamicSharedMemorySize, SMEM_3T);
    cudaFuncSetAttribute(k_gemm<1>, cudaFuncAttributeMaxDynamicSharedMemorySize, SMEM_3T);
    cudaFuncSetAttribute(k_gemm<2>, cudaFuncAttributeMaxDynamicSharedMemorySize, SMEM_3T);
    cudaFuncSetAttribute(k_gemm<3>, cudaFuncAttributeMaxDynamicSharedMemorySize, SMEM_2T);

    __half *hh, *hl, *wh, *wl;
    cudaGetSymbolAddress((void**)&hh, g_hh);
    cudaGetSymbolAddress((void**)&hl, g_hl);
    cudaGetSymbolAddress((void**)&wh, g_Wh);
    cudaGetSymbolAddress((void**)&wl, g_Wl);

    // 0) pre-split inputs
    k_split<<<(MROWS * Cc / 4) / 256, 256>>>(h,   hh, hl, MROWS * Cc / 4);
    k_split<<<(Cc * Cc / 4) / 256,    256>>>(W_w, wh, wl, Cc * Cc / 4);
    k_splitMt<<<1, 256>>>(Mmat);

    // 1) X = h @ W^T + b          -> X_hi/X_lo          (3-term f16)
    k_gemm<0><<<dim3(Hh, MROWS / 256), 256, SMEM_3T>>>(W_b);
    // 2) X^T                      -> VT_hi/VT_lo
    k_transpose<<<dim3(Nn / 32, Dd / 32, BHn), dim3(32, 8)>>>();
    // 3) XM = X @ M               -> XM_hi/XM_lo        (3-term f16)
    k_gemm<1><<<dim3((BHn * Nn) / 256), 256, SMEM_3T>>>(nullptr);
    // 4) P = exp(S - 12), lpart   -> g_Ph (fp16), g_L   (3-term f16)
    k_gemm<2><<<dim3(Nn / 128, Nn / 256, BHn), 256, SMEM_3T>>>(nullptr);
    // 5) O = (P @ V) / l          -> g_O                (2-term f16)
    k_gemm<3><<<dim3(Nn / 256, BHn), 256, SMEM_2T>>>(nullptr);
    // 6) LayerNorm + GELU         -> out
    k_ln_gelu<<<MROWS, 256>>>(gamma, beta, out);
}

// round 10
// speedup vs baseline: 4.2857x; 1.2223x over previous
#include <cuda_runtime.h>
#include <cuda_fp16.h>
#include <stdint.h>
#include <math.h>

// Fixed shapes for GraphAttentionLayer_18021682774974
#define Bb  32
#define Nn  1024
#define Cc  1024
#define Hh  8
#define Dd  128
#define BHn 256
#define MROWS (Bb * Nn)              // 32768
#define XW  (BHn * Nn * Dd)          // 33.5M

// log-domain shift so P = exp(S - PSHIFT) fits fp16 (S_max ~ 16 << 23.1).
// Cancels exactly in O = (P@V) / rowsum(P).
#define PSHIFT 12.0f

// Pre-split half operands + scratch (device globals; no cudaMalloc allowed)
__device__ __half g_hh [MROWS * Cc], g_hl [MROWS * Cc];   // h split
__device__ __half g_Wh [Cc * Cc],    g_Wl [Cc * Cc];      // W split
__device__ __half g_Mth[Dd * Dd],    g_Mtl[Dd * Dd];      // M^T split
__device__ __half g_Xh [XW], g_Xl [XW];                   // X  [z][n][d]
__device__ __half g_XMh[XW];                              // XM hi only
__device__ __half g_VTh[XW], g_VTl[XW];                   // X^T [z][d][n]
__device__ __half g_Ph [(size_t)BHn * Nn * Nn];           // P fp16 (512MB)
__device__ float  g_L  [BHn * Nn * 8];                    // row-sum partials
__device__ float  g_O  [XW];                              // attention out

// ---------------------------------------------------------------------------
__device__ __forceinline__ uint32_t smem_u32(const void* p) {
    uint32_t a;
    asm("{ .reg .u64 t; cvta.to.shared.u64 t, %1; cvt.u32.u64 %0, t; }"
        : "=r"(a) : "l"(p));
    return a;
}
__device__ __forceinline__ void cp16(uint32_t sa, const void* gp) {
    asm volatile("cp.async.cg.shared.global [%0], [%1], 16;" :: "r"(sa), "l"(gp));
}
#define CP_COMMIT() asm volatile("cp.async.commit_group;" ::: "memory")
#define CP_WAIT1()  asm volatile("cp.async.wait_group 1;" ::: "memory")

#define MMA_F16(d, a, b)                                                      \
    asm volatile("mma.sync.aligned.m16n8k16.row.col.f32.f16.f16.f32 "         \
                 "{%0,%1,%2,%3}, {%4,%5,%6,%7}, {%8,%9}, {%0,%1,%2,%3};"      \
                 : "+f"((d)[0]), "+f"((d)[1]), "+f"((d)[2]), "+f"((d)[3])     \
                 : "r"((a)[0]), "r"((a)[1]), "r"((a)[2]), "r"((a)[3]),        \
                   "r"((b)[0]), "r"((b)[1]))

// ---------------------------------------------------------------------------
// Elementwise fp32 -> fp16 hi/lo split (vectorized float4)
// ---------------------------------------------------------------------------
__global__ void __launch_bounds__(256) k_split(const float* __restrict__ src,
                                               __half* __restrict__ hi,
                                               __half* __restrict__ lo, int n4)
{
    int i = blockIdx.x * 256 + threadIdx.x;
    if (i >= n4) return;
    float4 v = ((const float4*)src)[i];
    __half h0 = __float2half_rn(v.x), h1 = __float2half_rn(v.y);
    __half h2 = __float2half_rn(v.z), h3 = __float2half_rn(v.w);
    ((__half2*)hi)[2*i]   = __halves2half2(h0, h1);
    ((__half2*)hi)[2*i+1] = __halves2half2(h2, h3);
    ((__half2*)lo)[2*i]   = __floats2half2_rn(v.x - __half2float(h0),
                                              v.y - __half2float(h1));
    ((__half2*)lo)[2*i+1] = __floats2half2_rn(v.z - __half2float(h2),
                                              v.w - __half2float(h3));
}

// M^T split (tiny, one block)
__global__ void __launch_bounds__(256) k_splitMt(const float* __restrict__ M)
{
    for (int i = threadIdx.x; i < Dd * Dd; i += 256) {
        int e = i >> 7, k = i & 127;
        float v = M[k * Dd + e];
        __half h = __float2half_rn(v);
        g_Mth[i] = h;
        g_Mtl[i] = __float2half_rn(v - __half2float(h));
    }
}

// ===========================================================================
// Unified f16 GEMM, cp.async 3-stage pipeline.  D[128x128] = A @ B^T.
// CTA = 128 threads (4 warps, 2x2 of 64x64 warp tiles) -> 2 CTAs/SM.
// K-chunk = 32 halfs. 16B chunk (row r, ch of 4) at index (ch ^ ((r>>1)&3)).
// Stage words: ALO(modes 0,1): AH[2048] AL[2048] BH[2048] BL[2048] = 8192
//              else  (2,3):    AH[2048]           BH[2048] BL[2048] = 6144
// MODE 0: X  = h @ W^T + bias   3-term  K=1024  grid (8 heads, 256 mt)
// MODE 1: XM = X @ M            3-term  K=128   grid (2048)
// MODE 2: P  = exp(XMh@X^T-12)  2-term  K=128   grid (8 nt, 8 mt, 256 z)
// MODE 3: O  = (P @ V) / l      2-term  K=1024  grid (8 mt, 256 z)
// ===========================================================================
template<int MODE>
__global__ void __launch_bounds__(128, 2) k_gemm(const float* __restrict__ bias)
{
    extern __shared__ uint32_t smw[];
    constexpr bool ALO = (MODE <= 1);               // A has a lo plane
    constexpr int  STG = ALO ? 8192 : 6144;         // words per stage
    constexpr int  NC  = (MODE == 0 || MODE == 3) ? 32 : 4;
    constexpr int  BOFF = ALO ? 4096 : 2048;

    const int tid = threadIdx.x;
    const int wid = tid >> 5, lane = tid & 31;
    const int wm  = wid >> 1, wn = wid & 1;
    const int g   = lane >> 2, t = lane & 3;
    const uint32_t xr = (uint32_t)((g & 6) << 1);
    const uint32_t sbase = smem_u32(smw);

    int m0 = 0, n0 = 0; size_t z = 0;
    const __half *Ah = nullptr, *Al = nullptr, *Bh = nullptr, *Bl = nullptr;
    int Ast = 0, Bst = 0;
    if (MODE == 0) {
        m0 = blockIdx.y * 128; n0 = blockIdx.x * 128;
        Ah = g_hh + (size_t)m0 * Cc;  Al = g_hl + (size_t)m0 * Cc;  Ast = Cc;
        Bh = g_Wh + (size_t)n0 * Cc;  Bl = g_Wl + (size_t)n0 * Cc;  Bst = Cc;
    } else if (MODE == 1) {
        m0 = blockIdx.x * 128;
        Ah = g_Xh + (size_t)m0 * Dd;  Al = g_Xl + (size_t)m0 * Dd;  Ast = Dd;
        Bh = g_Mth;                   Bl = g_Mtl;                   Bst = Dd;
    } else if (MODE == 2) {
        z = blockIdx.z; m0 = blockIdx.y * 128; n0 = blockIdx.x * 128;
        Ah = g_XMh + (z * Nn + m0) * (size_t)Dd;  Ast = Dd;
        Bh = g_Xh  + (z * Nn + n0) * (size_t)Dd;
        Bl = g_Xl  + (z * Nn + n0) * (size_t)Dd;  Bst = Dd;
    } else {
        z = blockIdx.y; m0 = blockIdx.x * 128;
        Ah = g_Ph  + (z * Nn + m0) * (size_t)Nn;  Ast = Nn;
        Bh = g_VTh + z * (size_t)(Dd * Nn);
        Bl = g_VTl + z * (size_t)(Dd * Nn);       Bst = Nn;
    }

    float acc[4][8][4];
    #pragma unroll
    for (int a = 0; a < 4; ++a)
        #pragma unroll
        for (int b = 0; b < 8; ++b)
            #pragma unroll
            for (int c = 0; c < 4; ++c) acc[a][b][c] = 0.f;

    auto load_stage = [&](int st, int k0) {
        const uint32_t sb = sbase + (uint32_t)st * STG * 4;
        #pragma unroll
        for (int i = 0; i < 4; ++i) {                       // A: 128r x 4 chunks
            int idx = tid + (i << 7);
            int r = idx >> 2, ch = idx & 3;
            uint32_t d = sb + (uint32_t)(r * 16 + ((ch ^ ((r >> 1) & 3)) << 2)) * 4;
            const size_t go = (size_t)r * Ast + k0 + ch * 8;
            cp16(d, Ah + go);
            if (ALO) cp16(d + 2048 * 4, Al + go);
        }
        #pragma unroll
        for (int i = 0; i < 4; ++i) {                       // B: 128r x 4 chunks
            int idx = tid + (i << 7);
            int r = idx >> 2, ch = idx & 3;
            uint32_t d = sb + (uint32_t)(BOFF * 4)
                       + (uint32_t)(r * 16 + ((ch ^ ((r >> 1) & 3)) << 2)) * 4;
            const size_t go = (size_t)r * Bst + k0 + ch * 8;
            cp16(d, Bh + go);
            cp16(d + 2048 * 4, Bl + go);
        }
    };

    // prologue
    load_stage(0, 0);  CP_COMMIT();
    load_stage(1, 32); CP_COMMIT();

    for (int c = 0; c < NC; ++c) {
        CP_WAIT1();
        __syncthreads();
        if (c + 2 < NC) load_stage((c + 2) % 3, (c + 2) * 32);
        CP_COMMIT();

        const int st = c % 3;
        const uint32_t* AH = smw + st * STG;
        const uint32_t* AL = AH + 2048;
        const uint32_t* BH = smw + st * STG + BOFF;
        const uint32_t* BL = BH + 2048;

        #pragma unroll
        for (int ks = 0; ks < 2; ++ks) {
            const uint32_t w0 = (uint32_t)(ks * 8 + t) ^ xr;
            const uint32_t w1 = (uint32_t)(ks * 8 + t + 4) ^ xr;
            uint32_t ah[4][4], bb[8][2];
            #pragma unroll
            for (int mf = 0; mf < 4; ++mf) {
                int R0 = (wm * 64 + mf * 16 + g) * 16, R1 = R0 + 128;
                ah[mf][0] = AH[R0 + w0];
                ah[mf][1] = AH[R1 + w0];
                ah[mf][2] = AH[R0 + w1];
                ah[mf][3] = AH[R1 + w1];
            }
            #pragma unroll
            for (int nf = 0; nf < 8; ++nf) {
                int Rn = (wn * 64 + nf * 8 + g) * 16;
                bb[nf][0] = BH[Rn + w0];
                bb[nf][1] = BH[Rn + w1];
            }
            // term 1: A_hi x B_hi
            #pragma unroll
            for (int mf = 0; mf < 4; ++mf)
                #pragma unroll
                for (int nf = 0; nf < 8; ++nf)
                    MMA_F16(acc[mf][nf], ah[mf], bb[nf]);
            // term (3-term modes only): A_lo x B_hi   (B_hi still live)
            if (ALO) {
                uint32_t al[4][4];
                #pragma unroll
                for (int mf = 0; mf < 4; ++mf) {
                    int R0 = (wm * 64 + mf * 16 + g) * 16, R1 = R0 + 128;
                    al[mf][0] = AL[R0 + w0];
                    al[mf][1] = AL[R1 + w0];
                    al[mf][2] = AL[R0 + w1];
                    al[mf][3] = AL[R1 + w1];
                }
                #pragma unroll
                for (int mf = 0; mf < 4; ++mf)
                    #pragma unroll
                    for (int nf = 0; nf < 8; ++nf)
                        MMA_F16(acc[mf][nf], al[mf], bb[nf]);
            }
            // term 2: A_hi x B_lo
            #pragma unroll
            for (int nf = 0; nf < 8; ++nf) {
                int Rn = (wn * 64 + nf * 8 + g) * 16;
                bb[nf][0] = BL[Rn + w0];
                bb[nf][1] = BL[Rn + w1];
            }
            #pragma unroll
            for (int mf = 0; mf < 4; ++mf)
                #pragma unroll
                for (int nf = 0; nf < 8; ++nf)
                    MMA_F16(acc[mf][nf], ah[mf], bb[nf]);
        }
    }
    __syncthreads();

    // ---- epilogue ----
    if (MODE == 0) {
        const int head = blockIdx.x;
        #pragma unroll
        for (int mf = 0; mf < 4; ++mf)
            #pragma unroll
            for (int hh = 0; hh < 2; ++hh) {
                int m = m0 + wm * 64 + mf * 16 + g + 8 * hh;
                int bidx = m >> 10, tok = m & 1023;
                size_t ro = (((size_t)bidx * Hh + head) * Nn + tok) * Dd;
                #pragma unroll
                for (int nf = 0; nf < 8; ++nf) {
                    int col = wn * 64 + nf * 8 + 2 * t;
                    float v0 = acc[mf][nf][2*hh+0] + bias[n0 + col];
                    float v1 = acc[mf][nf][2*hh+1] + bias[n0 + col + 1];
                    __half h0 = __float2half_rn(v0), h1 = __float2half_rn(v1);
                    *(__half2*)(g_Xh + ro + col) = __halves2half2(h0, h1);
                    *(__half2*)(g_Xl + ro + col) =
                        __floats2half2_rn(v0 - __half2float(h0),
                                          v1 - __half2float(h1));
                }
            }
    } else if (MODE == 1) {
        #pragma unroll
        for (int mf = 0; mf < 4; ++mf)
            #pragma unroll
            for (int hh = 0; hh < 2; ++hh) {
                size_t ro = (size_t)(m0 + wm * 64 + mf * 16 + g + 8 * hh) * Dd;
                #pragma unroll
                for (int nf = 0; nf < 8; ++nf) {
                    int col = wn * 64 + nf * 8 + 2 * t;
                    __half h0 = __float2half_rn(acc[mf][nf][2*hh+0]);
                    __half h1 = __float2half_rn(acc[mf][nf][2*hh+1]);
                    *(__half2*)(g_XMh + ro + col) = __halves2half2(h0, h1);
                }
            }
    } else if (MODE == 2) {
        float rsum[4][2];
        #pragma unroll
        for (int mf = 0; mf < 4; ++mf) { rsum[mf][0] = 0.f; rsum[mf][1] = 0.f; }
        #pragma unroll
        for (int mf = 0; mf < 4; ++mf)
            #pragma unroll
            for (int hh = 0; hh < 2; ++hh) {
                int rm = wm * 64 + mf * 16 + g + 8 * hh;
                __half* dst = g_Ph + (z * Nn + m0 + rm) * (size_t)Nn + n0;
                #pragma unroll
                for (int nf = 0; nf < 8; ++nf) {
                    int col = wn * 64 + nf * 8 + 2 * t;
                    __half p0 = __float2half_rn(__expf(acc[mf][nf][2*hh+0] - PSHIFT));
                    __half p1 = __float2half_rn(__expf(acc[mf][nf][2*hh+1] - PSHIFT));
                    rsum[mf][hh] += __half2float(p0) + __half2float(p1);
                    *(__half2*)(dst + col) = __halves2half2(p0, p1);
                }
            }
        float* ssum = (float*)smw;   // alias stage smem (compute done)
        #pragma unroll
        for (int mf = 0; mf < 4; ++mf)
            #pragma unroll
            for (int hh = 0; hh < 2; ++hh) {
                float s = rsum[mf][hh];
                s += __shfl_xor_sync(0xffffffffu, s, 1);
                s += __shfl_xor_sync(0xffffffffu, s, 2);
                if (t == 0)
                    ssum[(wm * 64 + mf * 16 + g + 8 * hh) * 2 + wn] = s;
            }
        __syncthreads();
        {
            float l = ssum[tid * 2] + ssum[tid * 2 + 1];
            g_L[(z * Nn + m0 + tid) * 8 + blockIdx.x] = l;
        }
    } else {  // MODE 3 (PV)
        #pragma unroll
        for (int mf = 0; mf < 4; ++mf)
            #pragma unroll
            for (int hh = 0; hh < 2; ++hh) {
                size_t row = z * Nn + m0 + wm * 64 + mf * 16 + g + 8 * hh;
                const float* lp = g_L + row * 8;
                float l = ((lp[0] + lp[1]) + (lp[2] + lp[3]))
                        + ((lp[4] + lp[5]) + (lp[6] + lp[7]));
                float inv = 1.f / l;
                float* dst = g_O + row * (size_t)Dd;
                #pragma unroll
                for (int nf = 0; nf < 8; ++nf) {
                    int col = wn * 64 + nf * 8 + 2 * t;
                    *(float2*)(dst + col) =
                        make_float2(acc[mf][nf][2*hh+0] * inv,
                                    acc[mf][nf][2*hh+1] * inv);
                }
            }
    }
}

// ---------------------------------------------------------------------------
// Transpose X_hi/X_lo -> VT_hi/VT_lo  ([z][n][d] -> [z][d][n])
// ---------------------------------------------------------------------------
__global__ void __launch_bounds__(256) k_transpose()
{
    __shared__ __half th[32][33], tl[32][33];
    const int z  = blockIdx.z;
    const int d0 = blockIdx.y << 5;
    const int nb = blockIdx.x << 5;
    const int lx = threadIdx.x, ly = threadIdx.y;
    const __half* sh = g_Xh + (size_t)z * Nn * Dd;
    const __half* sl = g_Xl + (size_t)z * Nn * Dd;
    #pragma unroll
    for (int i = 0; i < 32; i += 8) {
        th[ly + i][lx] = sh[(size_t)(nb + ly + i) * Dd + d0 + lx];
        tl[ly + i][lx] = sl[(size_t)(nb + ly + i) * Dd + d0 + lx];
    }
    __syncthreads();
    __half* dh = g_VTh + (size_t)z * Dd * Nn;
    __half* dl = g_VTl + (size_t)z * Dd * Nn;
    #pragma unroll
    for (int i = 0; i < 32; i += 8) {
        dh[(size_t)(d0 + ly + i) * Nn + nb + lx] = th[lx][ly + i];
        dl[(size_t)(d0 + ly + i) * Nn + nb + lx] = tl[lx][ly + i];
    }
}

// ---------------------------------------------------------------------------
// LayerNorm + exact GELU over c (gather heads)
// ---------------------------------------------------------------------------
__global__ void __launch_bounds__(256) k_ln_gelu(const float* __restrict__ gamma,
                                                 const float* __restrict__ beta,
                                                 float* __restrict__ out)
{
    const int row = blockIdx.x;
    const int bbi = row >> 10, nn = row & 1023;
    const int tid = threadIdx.x;
    const int c0 = tid * 4, head = c0 >> 7, dd = c0 & 127;

    const float* src = g_O + (((size_t)bbi * Hh + head) * Nn + nn) * Dd + dd;
    float4 v = *(const float4*)src;

    float s = v.x + v.y + v.z + v.w;
    float q = v.x*v.x + v.y*v.y + v.z*v.z + v.w*v.w;
    #pragma unroll
    for (int off = 16; off >= 1; off >>= 1) {
        s += __shfl_xor_sync(0xffffffffu, s, off);
        q += __shfl_xor_sync(0xffffffffu, q, off);
    }
    __shared__ float ss[8], sq[8];
    if ((tid & 31) == 0) { ss[tid >> 5] = s; sq[tid >> 5] = q; }
    __syncthreads();
    float st = 0.f, qt = 0.f;
    #pragma unroll
    for (int k = 0; k < 8; ++k) { st += ss[k]; qt += sq[k]; }

    const float mean = st * (1.f / (float)Cc);
    const float var  = qt * (1.f / (float)Cc) - mean * mean;
    const float rstd = rsqrtf(var + 1e-5f);

    float4 gm = *(const float4*)(gamma + c0);
    float4 be = *(const float4*)(beta + c0);
    float y0 = (v.x - mean) * rstd * gm.x + be.x;
    float y1 = (v.y - mean) * rstd * gm.y + be.y;
    float y2 = (v.z - mean) * rstd * gm.z + be.z;
    float y3 = (v.w - mean) * rstd * gm.w + be.w;

    const float k2 = 0.70710678118654752440f;
    float4 rr;
    rr.x = 0.5f * y0 * (1.f + erff(y0 * k2));
    rr.y = 0.5f * y1 * (1.f + erff(y1 * k2));
    rr.z = 0.5f * y2 * (1.f + erff(y2 * k2));
    rr.w = 0.5f * y3 * (1.f + erff(y3 * k2));
    *(float4*)(out + (size_t)row * Cc + c0) = rr;
}

// ---------------------------------------------------------------------------
#define SMEM_3T (3 * 8192 * 4)    // 98304 B  (modes 0,1)
#define SMEM_2T (3 * 6144 * 4)    // 73728 B  (modes 2,3)

extern "C" void kernel_launch(void* const* d_in, const int* in_sizes, int n_in,
                              void* d_out, int out_size)
{
    const float* h     = (const float*)d_in[0];
    const float* W_w   = (const float*)d_in[1];
    const float* W_b   = (const float*)d_in[2];
    const float* Mmat  = (const float*)d_in[3];
    const float* gamma = (const float*)d_in[4];
    const float* beta  = (const float*)d_in[5];
    float* out = (float*)d_out;

    cudaFuncSetAttribute(k_gemm<0>, cudaFuncAttributeMaxDynamicSharedMemorySize, SMEM_3T);
    cudaFuncSetAttribute(k_gemm<1>, cudaFuncAttributeMaxDynamicSharedMemorySize, SMEM_3T);
    cudaFuncSetAttribute(k_gemm<2>, cudaFuncAttributeMaxDynamicSharedMemorySize, SMEM_2T);
    cudaFuncSetAttribute(k_gemm<3>, cudaFuncAttributeMaxDynamicSharedMemorySize, SMEM_2T);

    __half *hh, *hl, *wh, *wl;
    cudaGetSymbolAddress((void**)&hh, g_hh);
    cudaGetSymbolAddress((void**)&hl, g_hl);
    cudaGetSymbolAddress((void**)&wh, g_Wh);
    cudaGetSymbolAddress((void**)&wl, g_Wl);

    // 0) pre-split inputs
    k_split<<<(MROWS * Cc / 4) / 256, 256>>>(h,   hh, hl, MROWS * Cc / 4);
    k_split<<<(Cc * Cc / 4) / 256,    256>>>(W_w, wh, wl, Cc * Cc / 4);
    k_splitMt<<<1, 256>>>(Mmat);

    // 1) X = h @ W^T + b          -> X_hi/X_lo          (3-term f16)
    k_gemm<0><<<dim3(Hh, MROWS / 128), 128, SMEM_3T>>>(W_b);
    // 2) X^T                      -> VT_hi/VT_lo
    k_transpose<<<dim3(Nn / 32, Dd / 32, BHn), dim3(32, 8)>>>();
    // 3) XM = X @ M               -> XM_hi               (3-term f16)
    k_gemm<1><<<dim3((BHn * Nn) / 128), 128, SMEM_3T>>>(nullptr);
    // 4) P = exp(S - 12), lpart   -> g_Ph (fp16), g_L    (2-term f16)
    k_gemm<2><<<dim3(Nn / 128, Nn / 128, BHn), 128, SMEM_2T>>>(nullptr);
    // 5) O = (P @ V) / l          -> g_O                 (2-term f16)
    k_gemm<3><<<dim3(Nn / 128, BHn), 128, SMEM_2T>>>(nullptr);
    // 6) LayerNorm + GELU         -> out
    k_ln_gelu<<<MROWS, 256>>>(gamma, beta, out);
}